// round 2
// baseline (speedup 1.0000x reference)
#include <cuda_runtime.h>

#define DE 273
#define EPSV 1e-12f
#define C2F 0.17677669529663688f  // 1/(4*sqrt(2))

// ----- scratch (static device allocations; no cudaMalloc allowed) -----
__device__ float gQ[8192 * 256];
__device__ float gKp[8192 * 256];
__device__ float gV[8192 * 1024];
__device__ float gY[8192 * 1024];
__device__ float gS[1024 * DE * 64];   // [bh*16+c][273][64], per-chunk then exclusive prefix
__device__ float gZ[1024 * DE];        // [bh*16+c][273]

// ============================================================================
// SGEMM (NT): C[m][n] = sum_k A[m][k] * B[n][k].  A: MxK, B: NxK, row-major.
// 128x128 block, BK=8, 256 threads, 8x8 per-thread register tile.
// ============================================================================
__global__ void __launch_bounds__(256) sgemm_nt(
    const float* __restrict__ A, const float* __restrict__ B,
    float* __restrict__ C, int M, int N, int K)
{
    __shared__ float As[8][128];
    __shared__ float Bs[8][128];
    const int tid = threadIdx.x;
    const int bm = blockIdx.y * 128;
    const int bn = blockIdx.x * 128;
    const int tx = tid & 15, ty = tid >> 4;
    const int lr = tid >> 1;          // 0..127
    const int lk = (tid & 1) * 4;     // 0 or 4

    const float* Ap = A + (size_t)(bm + lr) * K + lk;
    const float* Bp = B + (size_t)(bn + lr) * K + lk;

    float acc[8][8];
#pragma unroll
    for (int r = 0; r < 8; ++r)
#pragma unroll
        for (int c = 0; c < 8; ++c) acc[r][c] = 0.f;

    for (int kt = 0; kt < K; kt += 8) {
        float4 av = *(const float4*)(Ap + kt);
        float4 bv = *(const float4*)(Bp + kt);
        As[lk + 0][lr] = av.x; As[lk + 1][lr] = av.y;
        As[lk + 2][lr] = av.z; As[lk + 3][lr] = av.w;
        Bs[lk + 0][lr] = bv.x; Bs[lk + 1][lr] = bv.y;
        Bs[lk + 2][lr] = bv.z; Bs[lk + 3][lr] = bv.w;
        __syncthreads();
#pragma unroll
        for (int k = 0; k < 8; ++k) {
            float4 a0 = *(const float4*)&As[k][ty * 8];
            float4 a1 = *(const float4*)&As[k][ty * 8 + 4];
            float4 b0 = *(const float4*)&Bs[k][tx * 8];
            float4 b1 = *(const float4*)&Bs[k][tx * 8 + 4];
            float am[8] = {a0.x, a0.y, a0.z, a0.w, a1.x, a1.y, a1.z, a1.w};
            float bb[8] = {b0.x, b0.y, b0.z, b0.w, b1.x, b1.y, b1.z, b1.w};
#pragma unroll
            for (int r = 0; r < 8; ++r)
#pragma unroll
                for (int c = 0; c < 8; ++c) acc[r][c] += am[r] * bb[c];
        }
        __syncthreads();
    }

#pragma unroll
    for (int r = 0; r < 8; ++r) {
        float* Cp = C + (size_t)(bm + ty * 8 + r) * N + bn + tx * 8;
        *(float4*)Cp       = make_float4(acc[r][0], acc[r][1], acc[r][2], acc[r][3]);
        *(float4*)(Cp + 4) = make_float4(acc[r][4], acc[r][5], acc[r][6], acc[r][7]);
    }
}

// ============================================================================
// Phase A: per-(b,h,chunk) state contribution S_c = kf^T @ v, z_c = sum_j kf_j
// grid = 1024 (bh*16+c), 256 threads. Feature map computed on the fly per tile.
// dynamic smem: sK 128*17 | sV 128*65 | sKF 128*33  (58880 bytes)
// ============================================================================
__global__ void __launch_bounds__(256) chunk_state_kernel()
{
    extern __shared__ float sm[];
    float* sK  = sm;                 // 2176
    float* sV  = sm + 2176;          // 8320
    float* sKF = sm + 2176 + 8320;   // 4224

    const int bid = blockIdx.x;
    const int bh = bid >> 4, c = bid & 15;
    const int b = bh >> 4, h = bh & 15;
    const int tid = threadIdx.x;
    const int m0 = b * 2048 + c * 128;

    for (int idx = tid; idx < 2048; idx += 256) {
        int i = idx >> 4, f = idx & 15;
        sK[i * 17 + f] = gKp[(m0 + i) * 256 + h * 16 + f];
    }
    for (int idx = tid; idx < 8192; idx += 256) {
        int i = idx >> 6, e = idx & 63;
        sV[i * 65 + e] = gV[(m0 + i) * 1024 + h * 64 + e];
    }
    __syncthreads();

    float* outS = gS + (bh * 16 + c) * (DE * 64);
    float* outZ = gZ + (bh * 16 + c) * DE;
    const int e = tid & 63;
    const int dbase = tid >> 6;  // 0..3

    for (int dt = 0; dt < 9; ++dt) {
        const int width = (dt == 8) ? 17 : 32;
        const int d0 = dt * 32;
        // build kf tile [128][width]
        for (int idx = tid; idx < 128 * width; idx += 256) {
            int j = idx / width, dl = idx - j * width;
            int dg = d0 + dl;
            float val;
            if (dg == 0) val = 1.f;
            else if (dg < 17) val = sK[j * 17 + dg - 1] * 0.5f;
            else {
                int tq = dg - 17;
                val = sK[j * 17 + (tq >> 4)] * sK[j * 17 + (tq & 15)] * C2F;
            }
            sKF[j * 33 + dl] = val;
        }
        __syncthreads();

        float acc[8];
#pragma unroll
        for (int ii = 0; ii < 8; ++ii) acc[ii] = 0.f;
        for (int j = 0; j < 128; ++j) {
            float v = sV[j * 65 + e];
#pragma unroll
            for (int ii = 0; ii < 8; ++ii) {
                int dl = dbase + ii * 4;
                if (dl < width) acc[ii] += sKF[j * 33 + dl] * v;
            }
        }
#pragma unroll
        for (int ii = 0; ii < 8; ++ii) {
            int dl = dbase + ii * 4;
            if (dl < width) outS[(d0 + dl) * 64 + e] = acc[ii];
        }
        if (tid < width) {
            float az = 0.f;
            for (int j = 0; j < 128; ++j) az += sKF[j * 33 + tid];
            outZ[d0 + tid] = az;
        }
        __syncthreads();
    }
}

// ============================================================================
// Phase B: in-place EXCLUSIVE prefix over the 16 chunks for each (b,h).
// grid = 64 (bh), 256 threads.
// ============================================================================
__global__ void __launch_bounds__(256) prefix_kernel()
{
    const int bh = blockIdx.x;
    float* Sb = gS + bh * 16 * (DE * 64);
    for (int idx = threadIdx.x; idx < DE * 64; idx += 256) {
        float run = 0.f;
#pragma unroll
        for (int c = 0; c < 16; ++c) {
            float* p = Sb + c * (DE * 64) + idx;
            float tmp = *p;
            *p = run;
            run += tmp;
        }
    }
    float* Zb = gZ + bh * 16 * DE;
    for (int idx = threadIdx.x; idx < DE; idx += 256) {
        float run = 0.f;
#pragma unroll
        for (int c = 0; c < 16; ++c) {
            float* p = Zb + c * DE + idx;
            float tmp = *p;
            *p = run;
            run += tmp;
        }
    }
}

// ============================================================================
// Phase C: per-(b,h,chunk) output.
//   A_ij = mask * (1 + (q.k)/4 + (q.k)^2/32)    (closed form of qf.kf)
//   y = (A @ v + qf @ S_prefix) / (rowsum(A) + qf.z + eps)
// grid = 1024, 256 threads. Thread (ty,tx): rows ty*8..+7, cols tx*4..+3.
// dynamic smem: sQ 2176 | sK 2176 | sV 8320 | sT 4224 | sS 2080 | sZ 32 (76032 B)
// ============================================================================
__global__ void __launch_bounds__(256) chunk_out_kernel()
{
    extern __shared__ float sm[];
    float* sQ = sm;             // 2176
    float* sK = sm + 2176;      // 2176
    float* sV = sm + 4352;      // 8320
    float* sT = sm + 12672;     // 4224
    float* sS = sm + 16896;     // 2080
    float* sZ = sm + 18976;     // 32

    const int bid = blockIdx.x;
    const int bh = bid >> 4, c = bid & 15;
    const int b = bh >> 4, h = bh & 15;
    const int tid = threadIdx.x;
    const int tx = tid & 15, ty = tid >> 4;
    const int m0 = b * 2048 + c * 128;

    for (int idx = tid; idx < 2048; idx += 256) {
        int i = idx >> 4, f = idx & 15;
        sQ[i * 17 + f] = gQ[(m0 + i) * 256 + h * 16 + f];
        sK[i * 17 + f] = gKp[(m0 + i) * 256 + h * 16 + f];
    }
    for (int idx = tid; idx < 8192; idx += 256) {
        int i = idx >> 6, e = idx & 63;
        sV[i * 65 + e] = gV[(m0 + i) * 1024 + h * 64 + e];
    }
    __syncthreads();

    float accY[8][4];
    float accD[8];
#pragma unroll
    for (int r = 0; r < 8; ++r) {
        accD[r] = 0.f;
#pragma unroll
        for (int cc = 0; cc < 4; ++cc) accY[r][cc] = 0.f;
    }

    // ---- intra-chunk: masked A @ V and rowsum(A) ----
    for (int jt = 0; jt < 4; ++jt) {
        for (int idx = tid; idx < 4096; idx += 256) {
            int i = idx >> 5, jl = idx & 31;
            int j = jt * 32 + jl;
            float dot = 0.f;
#pragma unroll
            for (int f = 0; f < 16; ++f) dot += sQ[i * 17 + f] * sK[j * 17 + f];
            float a = 1.f + dot * 0.25f + dot * dot * 0.03125f;
            sT[i * 33 + jl] = (j <= i) ? a : 0.f;
        }
        __syncthreads();
        for (int jl = 0; jl < 32; ++jl) {
            int j = jt * 32 + jl;
            float v0 = sV[j * 65 + tx * 4 + 0];
            float v1 = sV[j * 65 + tx * 4 + 1];
            float v2 = sV[j * 65 + tx * 4 + 2];
            float v3 = sV[j * 65 + tx * 4 + 3];
#pragma unroll
            for (int r = 0; r < 8; ++r) {
                float a = sT[(ty * 8 + r) * 33 + jl];
                accD[r] += a;
                accY[r][0] += a * v0; accY[r][1] += a * v1;
                accY[r][2] += a * v2; accY[r][3] += a * v3;
            }
        }
        __syncthreads();
    }

    // ---- inter-chunk: qf @ S_prefix and qf . z ----
    const float* Sp = gS + (bh * 16 + c) * (DE * 64);
    const float* Zp = gZ + (bh * 16 + c) * DE;
    for (int dt = 0; dt < 9; ++dt) {
        const int width = (dt == 8) ? 17 : 32;
        const int d0 = dt * 32;
        for (int idx = tid; idx < width * 64; idx += 256)
            sS[(idx >> 6) * 65 + (idx & 63)] = Sp[(d0 + (idx >> 6)) * 64 + (idx & 63)];
        if (tid < width) sZ[tid] = Zp[d0 + tid];
        for (int idx = tid; idx < 128 * width; idx += 256) {
            int i = idx / width, dl = idx - i * width;
            int dg = d0 + dl;
            float val;
            if (dg == 0) val = 1.f;
            else if (dg < 17) val = sQ[i * 17 + dg - 1] * 0.5f;
            else {
                int tq = dg - 17;
                val = sQ[i * 17 + (tq >> 4)] * sQ[i * 17 + (tq & 15)] * C2F;
            }
            sT[i * 33 + dl] = val;
        }
        __syncthreads();
        for (int dl = 0; dl < width; ++dl) {
            float s0 = sS[dl * 65 + tx * 4 + 0];
            float s1 = sS[dl * 65 + tx * 4 + 1];
            float s2 = sS[dl * 65 + tx * 4 + 2];
            float s3 = sS[dl * 65 + tx * 4 + 3];
            float zv = sZ[dl];
#pragma unroll
            for (int r = 0; r < 8; ++r) {
                float a = sT[(ty * 8 + r) * 33 + dl];
                accD[r] += a * zv;
                accY[r][0] += a * s0; accY[r][1] += a * s1;
                accY[r][2] += a * s2; accY[r][3] += a * s3;
            }
        }
        __syncthreads();
    }

    // ---- divide + store into y (layout [m][h*64+e] for the Wo GEMM) ----
#pragma unroll
    for (int r = 0; r < 8; ++r) {
        int i = ty * 8 + r;
        float inv = 1.f / (accD[r] + EPSV);
        float* yp = gY + (size_t)(m0 + i) * 1024 + h * 64 + tx * 4;
        yp[0] = accY[r][0] * inv;
        yp[1] = accY[r][1] * inv;
        yp[2] = accY[r][2] * inv;
        yp[3] = accY[r][3] * inv;
    }
}

// ============================================================================
// host launch
// ============================================================================
extern "C" void kernel_launch(void* const* d_in, const int* in_sizes, int n_in,
                              void* d_out, int out_size)
{
    const float* hs = (const float*)d_in[0];
    const float* Wq = (const float*)d_in[1];
    const float* Wk = (const float*)d_in[2];
    const float* Wv = (const float*)d_in[3];
    const float* Wo = (const float*)d_in[4];
    float* out = (float*)d_out;

    float *pQ, *pK, *pV, *pY;
    cudaGetSymbolAddress((void**)&pQ, gQ);
    cudaGetSymbolAddress((void**)&pK, gKp);
    cudaGetSymbolAddress((void**)&pV, gV);
    cudaGetSymbolAddress((void**)&pY, gY);

    const int SMEM_CS = 14720 * 4;   // 58880
    const int SMEM_CO = 19008 * 4;   // 76032
    cudaFuncSetAttribute(chunk_state_kernel,
                         cudaFuncAttributeMaxDynamicSharedMemorySize, SMEM_CS);
    cudaFuncSetAttribute(chunk_out_kernel,
                         cudaFuncAttributeMaxDynamicSharedMemorySize, SMEM_CO);

    dim3 blk(256);
    // projections
    sgemm_nt<<<dim3(2, 64), blk>>>(hs, Wq, pQ, 8192, 256, 1024);
    sgemm_nt<<<dim3(2, 64), blk>>>(hs, Wk, pK, 8192, 256, 1024);
    sgemm_nt<<<dim3(8, 64), blk>>>(hs, Wv, pV, 8192, 1024, 1024);
    // chunked linear attention
    chunk_state_kernel<<<1024, 256, SMEM_CS>>>();
    prefix_kernel<<<64, 256>>>();
    chunk_out_kernel<<<1024, 256, SMEM_CO>>>();
    // output projection
    sgemm_nt<<<dim3(8, 64), blk>>>(pY, Wo, out, 8192, 1024, 1024);
}

// round 4
// speedup vs baseline: 1.7544x; 1.7544x over previous
#include <cuda_runtime.h>
#include <cuda_bf16.h>
#include <cstdint>

#define DE 273
#define EPSV 1e-12f
#define C2F 0.17677669529663688f  // 1/(4*sqrt(2))

// ----- scratch (static device allocations; no cudaMalloc allowed) -----
__device__ float gQK[8192 * 512];      // [m][h*16+f] Q at col 0..255, K at 256..511
__device__ float gV[8192 * 1024];
__device__ float gS[1024 * DE * 64];   // [bh*16+c][273][64]
__device__ float gZ[1024 * DE];        // [bh*16+c][273]
__device__ __nv_bfloat16 gHh[8192 * 1024];
__device__ __nv_bfloat16 gHl[8192 * 1024];
__device__ __nv_bfloat16 gWh[1024 * 1024];
__device__ __nv_bfloat16 gWl[1024 * 1024];
__device__ __nv_bfloat16 gYh[8192 * 1024];
__device__ __nv_bfloat16 gYl[8192 * 1024];

// ============================================================================
// helpers (portable PTX only: cp.async / ldmatrix / mma.sync)
// ============================================================================
__device__ __forceinline__ uint32_t smem_u32(const void* p) {
    uint32_t a;
    asm("{ .reg .u64 t; cvta.to.shared.u64 t, %1; cvt.u32.u64 %0, t; }" : "=r"(a) : "l"(p));
    return a;
}
__device__ __forceinline__ void cpasync16(uint32_t dst, const void* src) {
    asm volatile("cp.async.cg.shared.global [%0], [%1], 16;" :: "r"(dst), "l"(src));
}
__device__ __forceinline__ void cpasync_commit() {
    asm volatile("cp.async.commit_group;" ::: "memory");
}
__device__ __forceinline__ void cpasync_wait_all() {
    asm volatile("cp.async.wait_group 0;" ::: "memory");
}
__device__ __forceinline__ void ldsm4(uint32_t* r, uint32_t addr) {
    asm volatile("ldmatrix.sync.aligned.m8n8.x4.shared.b16 {%0,%1,%2,%3}, [%4];"
        : "=r"(r[0]), "=r"(r[1]), "=r"(r[2]), "=r"(r[3]) : "r"(addr));
}
__device__ __forceinline__ void mma_bf16(float* d, const uint32_t* a, const uint32_t* b) {
    asm volatile(
        "mma.sync.aligned.m16n8k16.row.col.f32.bf16.bf16.f32 "
        "{%0,%1,%2,%3}, {%4,%5,%6,%7}, {%8,%9}, {%0,%1,%2,%3};"
        : "+f"(d[0]), "+f"(d[1]), "+f"(d[2]), "+f"(d[3])
        : "r"(a[0]), "r"(a[1]), "r"(a[2]), "r"(a[3]), "r"(b[0]), "r"(b[1]));
}
__device__ __forceinline__ uint32_t sw128(uint32_t bo) { return bo ^ ((bo >> 3) & 0x70); }

// ============================================================================
// fp32 -> (hi, lo) bf16 split conversion.  one block = 1024 elements.
// ============================================================================
__global__ void __launch_bounds__(256) cvt_hilo(
    const float* __restrict__ src, __nv_bfloat16* __restrict__ hi,
    __nv_bfloat16* __restrict__ lo)
{
    int i = (blockIdx.x * 256 + threadIdx.x) * 4;
    float4 v = *(const float4*)(src + i);
    __nv_bfloat16 h0 = __float2bfloat16(v.x), h1 = __float2bfloat16(v.y);
    __nv_bfloat16 h2 = __float2bfloat16(v.z), h3 = __float2bfloat16(v.w);
    __nv_bfloat16 l0 = __float2bfloat16(v.x - __bfloat162float(h0));
    __nv_bfloat16 l1 = __float2bfloat16(v.y - __bfloat162float(h1));
    __nv_bfloat16 l2 = __float2bfloat16(v.z - __bfloat162float(h2));
    __nv_bfloat16 l3 = __float2bfloat16(v.w - __bfloat162float(h3));
    __nv_bfloat162* ph = (__nv_bfloat162*)(hi + i);
    __nv_bfloat162* pl = (__nv_bfloat162*)(lo + i);
    ph[0] = __nv_bfloat162(h0, h1); ph[1] = __nv_bfloat162(h2, h3);
    pl[0] = __nv_bfloat162(l0, l1); pl[1] = __nv_bfloat162(l2, l3);
}

// ============================================================================
// split-bf16 HMMA GEMM (NT): C[m][n] = sum_k A[m][k]*B[n][k], fp32-quality.
// C = Ah*Bh + Ah*Bl + Al*Bh.  CTA tile 128x128, K in stages of 64.
// cp.async double-buffered SMEM (2 x 64KB), 8 warps, warp tile 32x64.
// ============================================================================
__global__ void __launch_bounds__(256) gemm_mma(
    const __nv_bfloat16* __restrict__ Ah, const __nv_bfloat16* __restrict__ Al,
    const __nv_bfloat16* __restrict__ Bh, const __nv_bfloat16* __restrict__ Bl,
    float* __restrict__ C, int N, int K)
{
    extern __shared__ char smem[];
    const uint32_t sb = smem_u32(smem);
    const int tid = threadIdx.x, wid = tid >> 5, l = tid & 31;
    const int wm = wid & 3, wn = wid >> 2;
    const int bm = blockIdx.y * 128, bn = blockIdx.x * 128;

    const __nv_bfloat16* gp0[4] = {
        Ah + (size_t)bm * K, Al + (size_t)bm * K,
        Bh + (size_t)bn * K, Bl + (size_t)bn * K };

    // per-thread load slots: 4 chunks/tile (row = ch>>3, 16B chunk = ch&7)
    // stage issue helper (inlined via lambda-free macro style)
    const int NST = K >> 6;

    float acc[2][8][4];
#pragma unroll
    for (int mt = 0; mt < 2; ++mt)
#pragma unroll
        for (int nt = 0; nt < 8; ++nt)
#pragma unroll
            for (int c = 0; c < 4; ++c) acc[mt][nt][c] = 0.f;

    // ---- issue stage 0 ----
    {
        const uint32_t sdst = sb;
#pragma unroll
        for (int t = 0; t < 4; ++t)
#pragma unroll
            for (int it = 0; it < 4; ++it) {
                int ch = tid + it * 256;
                int row = ch >> 3, cb = ch & 7;
                cpasync16(sdst + t * 16384 + sw128(row * 128 + cb * 16),
                          gp0[t] + (size_t)row * K + cb * 8);
            }
        cpasync_commit();
    }

    for (int s = 0; s < NST; ++s) {
        cpasync_wait_all();
        __syncthreads();
        // prefetch next stage
        if (s + 1 < NST) {
            const uint32_t sdst = sb + (uint32_t)((s + 1) & 1) * 65536u;
            const int k0 = (s + 1) * 64;
#pragma unroll
            for (int t = 0; t < 4; ++t)
#pragma unroll
                for (int it = 0; it < 4; ++it) {
                    int ch = tid + it * 256;
                    int row = ch >> 3, cb = ch & 7;
                    cpasync16(sdst + t * 16384 + sw128(row * 128 + cb * 16),
                              gp0[t] + (size_t)row * K + k0 + cb * 8);
                }
            cpasync_commit();
        }
        // compute on buffer s&1
        const uint32_t sc = sb + (uint32_t)(s & 1) * 65536u;
#pragma unroll
        for (int ks = 0; ks < 4; ++ks) {
            uint32_t ah[2][4], al[2][4], bh[8][2], bl[8][2];
#pragma unroll
            for (int mt = 0; mt < 2; ++mt) {
                uint32_t bo = (uint32_t)(wm * 32 + mt * 16 + (l & 15)) * 128
                            + ks * 32 + ((l >> 4) << 4);
                bo = sw128(bo);
                ldsm4(ah[mt], sc + bo);
                ldsm4(al[mt], sc + 16384 + bo);
            }
#pragma unroll
            for (int p = 0; p < 4; ++p) {
                uint32_t n = (uint32_t)(wn * 64 + p * 16 + (l & 7) + ((l >> 4) << 3));
                uint32_t bo = n * 128 + ks * 32 + (((l >> 3) & 1) << 4);
                bo = sw128(bo);
                uint32_t r[4];
                ldsm4(r, sc + 32768 + bo);
                bh[2 * p][0] = r[0]; bh[2 * p][1] = r[1];
                bh[2 * p + 1][0] = r[2]; bh[2 * p + 1][1] = r[3];
                ldsm4(r, sc + 49152 + bo);
                bl[2 * p][0] = r[0]; bl[2 * p][1] = r[1];
                bl[2 * p + 1][0] = r[2]; bl[2 * p + 1][1] = r[3];
            }
#pragma unroll
            for (int mt = 0; mt < 2; ++mt)
#pragma unroll
                for (int nt = 0; nt < 8; ++nt) mma_bf16(acc[mt][nt], ah[mt], bh[nt]);
#pragma unroll
            for (int mt = 0; mt < 2; ++mt)
#pragma unroll
                for (int nt = 0; nt < 8; ++nt) mma_bf16(acc[mt][nt], ah[mt], bl[nt]);
#pragma unroll
            for (int mt = 0; mt < 2; ++mt)
#pragma unroll
                for (int nt = 0; nt < 8; ++nt) mma_bf16(acc[mt][nt], al[mt], bh[nt]);
        }
        __syncthreads();
    }

    // writeback
    const int r0 = bm + wm * 32 + (l >> 2);
    const int c0 = bn + wn * 64 + 2 * (l & 3);
#pragma unroll
    for (int mt = 0; mt < 2; ++mt)
#pragma unroll
        for (int nt = 0; nt < 8; ++nt) {
            float* p0 = C + (size_t)(r0 + mt * 16) * N + c0 + nt * 8;
            float* p1 = C + (size_t)(r0 + mt * 16 + 8) * N + c0 + nt * 8;
            *(float2*)p0 = make_float2(acc[mt][nt][0], acc[mt][nt][1]);
            *(float2*)p1 = make_float2(acc[mt][nt][2], acc[mt][nt][3]);
        }
}

// ============================================================================
// Phase A: per-(b,h,chunk) state contribution S_c = kf^T @ v, z_c = sum_j kf_j
// ============================================================================
__global__ void __launch_bounds__(256) chunk_state_kernel()
{
    extern __shared__ float sm[];
    float* sK  = sm;                 // 2176
    float* sV  = sm + 2176;          // 8320
    float* sKF = sm + 2176 + 8320;   // 4224

    const int bid = blockIdx.x;
    const int bh = bid >> 4, c = bid & 15;
    const int b = bh >> 4, h = bh & 15;
    const int tid = threadIdx.x;
    const int m0 = b * 2048 + c * 128;

    for (int idx = tid; idx < 2048; idx += 256) {
        int i = idx >> 4, f = idx & 15;
        sK[i * 17 + f] = gQK[(m0 + i) * 512 + 256 + h * 16 + f];
    }
    for (int idx = tid; idx < 8192; idx += 256) {
        int i = idx >> 6, e = idx & 63;
        sV[i * 65 + e] = gV[(m0 + i) * 1024 + h * 64 + e];
    }
    __syncthreads();

    float* outS = gS + (bh * 16 + c) * (DE * 64);
    float* outZ = gZ + (bh * 16 + c) * DE;
    const int e = tid & 63;
    const int dbase = tid >> 6;  // 0..3

    for (int dt = 0; dt < 9; ++dt) {
        const int width = (dt == 8) ? 17 : 32;
        const int d0 = dt * 32;
        for (int idx = tid; idx < 128 * width; idx += 256) {
            int j = idx / width, dl = idx - j * width;
            int dg = d0 + dl;
            float val;
            if (dg == 0) val = 1.f;
            else if (dg < 17) val = sK[j * 17 + dg - 1] * 0.5f;
            else {
                int tq = dg - 17;
                val = sK[j * 17 + (tq >> 4)] * sK[j * 17 + (tq & 15)] * C2F;
            }
            sKF[j * 33 + dl] = val;
        }
        __syncthreads();

        float acc[8];
#pragma unroll
        for (int ii = 0; ii < 8; ++ii) acc[ii] = 0.f;
        for (int j = 0; j < 128; ++j) {
            float v = sV[j * 65 + e];
#pragma unroll
            for (int ii = 0; ii < 8; ++ii) {
                int dl = dbase + ii * 4;
                if (dl < width) acc[ii] += sKF[j * 33 + dl] * v;
            }
        }
#pragma unroll
        for (int ii = 0; ii < 8; ++ii) {
            int dl = dbase + ii * 4;
            if (dl < width) outS[(d0 + dl) * 64 + e] = acc[ii];
        }
        if (tid < width) {
            float az = 0.f;
            for (int j = 0; j < 128; ++j) az += sKF[j * 33 + tid];
            outZ[d0 + tid] = az;
        }
        __syncthreads();
    }
}

// ============================================================================
// Phase B: exclusive prefix over 16 chunks per (b,h)
// ============================================================================
__global__ void __launch_bounds__(256) prefix_kernel()
{
    const int bh = blockIdx.x;
    float* Sb = gS + bh * 16 * (DE * 64);
    for (int idx = threadIdx.x; idx < DE * 64; idx += 256) {
        float run = 0.f;
#pragma unroll
        for (int c = 0; c < 16; ++c) {
            float* p = Sb + c * (DE * 64) + idx;
            float tmp = *p;
            *p = run;
            run += tmp;
        }
    }
    float* Zb = gZ + bh * 16 * DE;
    for (int idx = threadIdx.x; idx < DE; idx += 256) {
        float run = 0.f;
#pragma unroll
        for (int c = 0; c < 16; ++c) {
            float* p = Zb + c * DE + idx;
            float tmp = *p;
            *p = run;
            run += tmp;
        }
    }
}

// ============================================================================
// Phase C: per-(b,h,chunk) output; writes y as bf16 hi/lo for the Wo GEMM.
// ============================================================================
__global__ void __launch_bounds__(256) chunk_out_kernel()
{
    extern __shared__ float sm[];
    float* sQ = sm;             // 2176
    float* sK = sm + 2176;      // 2176
    float* sV = sm + 4352;      // 8320
    float* sT = sm + 12672;     // 4224
    float* sS = sm + 16896;     // 2080
    float* sZ = sm + 18976;     // 32

    const int bid = blockIdx.x;
    const int bh = bid >> 4, c = bid & 15;
    const int b = bh >> 4, h = bh & 15;
    const int tid = threadIdx.x;
    const int tx = tid & 15, ty = tid >> 4;
    const int m0 = b * 2048 + c * 128;

    for (int idx = tid; idx < 2048; idx += 256) {
        int i = idx >> 4, f = idx & 15;
        sQ[i * 17 + f] = gQK[(m0 + i) * 512 + h * 16 + f];
        sK[i * 17 + f] = gQK[(m0 + i) * 512 + 256 + h * 16 + f];
    }
    for (int idx = tid; idx < 8192; idx += 256) {
        int i = idx >> 6, e = idx & 63;
        sV[i * 65 + e] = gV[(m0 + i) * 1024 + h * 64 + e];
    }
    __syncthreads();

    float accY[8][4];
    float accD[8];
#pragma unroll
    for (int r = 0; r < 8; ++r) {
        accD[r] = 0.f;
#pragma unroll
        for (int cc = 0; cc < 4; ++cc) accY[r][cc] = 0.f;
    }

    // intra-chunk
    for (int jt = 0; jt < 4; ++jt) {
        for (int idx = tid; idx < 4096; idx += 256) {
            int i = idx >> 5, jl = idx & 31;
            int j = jt * 32 + jl;
            float dot = 0.f;
#pragma unroll
            for (int f = 0; f < 16; ++f) dot += sQ[i * 17 + f] * sK[j * 17 + f];
            float a = 1.f + dot * 0.25f + dot * dot * 0.03125f;
            sT[i * 33 + jl] = (j <= i) ? a : 0.f;
        }
        __syncthreads();
        for (int jl = 0; jl < 32; ++jl) {
            int j = jt * 32 + jl;
            float v0 = sV[j * 65 + tx * 4 + 0];
            float v1 = sV[j * 65 + tx * 4 + 1];
            float v2 = sV[j * 65 + tx * 4 + 2];
            float v3 = sV[j * 65 + tx * 4 + 3];
#pragma unroll
            for (int r = 0; r < 8; ++r) {
                float a = sT[(ty * 8 + r) * 33 + jl];
                accD[r] += a;
                accY[r][0] += a * v0; accY[r][1] += a * v1;
                accY[r][2] += a * v2; accY[r][3] += a * v3;
            }
        }
        __syncthreads();
    }

    // inter-chunk
    const float* Sp = gS + (bh * 16 + c) * (DE * 64);
    const float* Zp = gZ + (bh * 16 + c) * DE;
    for (int dt = 0; dt < 9; ++dt) {
        const int width = (dt == 8) ? 17 : 32;
        const int d0 = dt * 32;
        for (int idx = tid; idx < width * 64; idx += 256)
            sS[(idx >> 6) * 65 + (idx & 63)] = Sp[(d0 + (idx >> 6)) * 64 + (idx & 63)];
        if (tid < width) sZ[tid] = Zp[d0 + tid];
        for (int idx = tid; idx < 128 * width; idx += 256) {
            int i = idx / width, dl = idx - i * width;
            int dg = d0 + dl;
            float val;
            if (dg == 0) val = 1.f;
            else if (dg < 17) val = sQ[i * 17 + dg - 1] * 0.5f;
            else {
                int tq = dg - 17;
                val = sQ[i * 17 + (tq >> 4)] * sQ[i * 17 + (tq & 15)] * C2F;
            }
            sT[i * 33 + dl] = val;
        }
        __syncthreads();
        for (int dl = 0; dl < width; ++dl) {
            float s0 = sS[dl * 65 + tx * 4 + 0];
            float s1 = sS[dl * 65 + tx * 4 + 1];
            float s2 = sS[dl * 65 + tx * 4 + 2];
            float s3 = sS[dl * 65 + tx * 4 + 3];
            float zv = sZ[dl];
#pragma unroll
            for (int r = 0; r < 8; ++r) {
                float a = sT[(ty * 8 + r) * 33 + dl];
                accD[r] += a * zv;
                accY[r][0] += a * s0; accY[r][1] += a * s1;
                accY[r][2] += a * s2; accY[r][3] += a * s3;
            }
        }
        __syncthreads();
    }

    // divide + store y as bf16 hi/lo
#pragma unroll
    for (int r = 0; r < 8; ++r) {
        int i = ty * 8 + r;
        float inv = 1.f / (accD[r] + EPSV);
        size_t base = (size_t)(m0 + i) * 1024 + h * 64 + tx * 4;
        __nv_bfloat16* yh = gYh + base;
        __nv_bfloat16* yl = gYl + base;
#pragma unroll
        for (int cc = 0; cc < 4; ++cc) {
            float yv = accY[r][cc] * inv;
            __nv_bfloat16 hv = __float2bfloat16(yv);
            yh[cc] = hv;
            yl[cc] = __float2bfloat16(yv - __bfloat162float(hv));
        }
    }
}

// ============================================================================
// host launch
// ============================================================================
extern "C" void kernel_launch(void* const* d_in, const int* in_sizes, int n_in,
                              void* d_out, int out_size)
{
    const float* hs = (const float*)d_in[0];
    const float* Wq = (const float*)d_in[1];
    const float* Wk = (const float*)d_in[2];
    const float* Wv = (const float*)d_in[3];
    const float* Wo = (const float*)d_in[4];
    float* out = (float*)d_out;

    float *pQK, *pV;
    __nv_bfloat16 *pHh, *pHl, *pWh, *pWl, *pYh, *pYl;
    cudaGetSymbolAddress((void**)&pQK, gQK);
    cudaGetSymbolAddress((void**)&pV, gV);
    cudaGetSymbolAddress((void**)&pHh, gHh);
    cudaGetSymbolAddress((void**)&pHl, gHl);
    cudaGetSymbolAddress((void**)&pWh, gWh);
    cudaGetSymbolAddress((void**)&pWl, gWl);
    cudaGetSymbolAddress((void**)&pYh, gYh);
    cudaGetSymbolAddress((void**)&pYl, gYl);

    const int SMEM_G  = 131072;     // 2 x 64KB stages
    const int SMEM_CS = 14720 * 4;  // 58880
    const int SMEM_CO = 19008 * 4;  // 76032
    cudaFuncSetAttribute(gemm_mma,
                         cudaFuncAttributeMaxDynamicSharedMemorySize, SMEM_G);
    cudaFuncSetAttribute(chunk_state_kernel,
                         cudaFuncAttributeMaxDynamicSharedMemorySize, SMEM_CS);
    cudaFuncSetAttribute(chunk_out_kernel,
                         cudaFuncAttributeMaxDynamicSharedMemorySize, SMEM_CO);

    dim3 blk(256);
    // hidden -> hi/lo bf16
    cvt_hilo<<<8192, blk>>>(hs, pHh, pHl);

    // fused Q|K projection (N = 512)
    cvt_hilo<<<256, blk>>>(Wq, pWh, pWl);
    cvt_hilo<<<256, blk>>>(Wk, pWh + 256 * 1024, pWl + 256 * 1024);
    gemm_mma<<<dim3(4, 64), blk, SMEM_G>>>(pHh, pHl, pWh, pWl, pQK, 512, 1024);

    // V projection
    cvt_hilo<<<1024, blk>>>(Wv, pWh, pWl);
    gemm_mma<<<dim3(8, 64), blk, SMEM_G>>>(pHh, pHl, pWh, pWl, pV, 1024, 1024);

    // chunked linear attention
    chunk_state_kernel<<<1024, 256, SMEM_CS>>>();
    prefix_kernel<<<64, 256>>>();
    chunk_out_kernel<<<1024, 256, SMEM_CO>>>();

    // output projection
    cvt_hilo<<<1024, blk>>>(Wo, pWh, pWl);
    gemm_mma<<<dim3(8, 64), blk, SMEM_G>>>(pYh, pYl, pWh, pWl, out, 1024, 1024);
}

// round 5
// speedup vs baseline: 2.1099x; 1.2027x over previous
#include <cuda_runtime.h>
#include <cuda_bf16.h>
#include <cstdint>

#define DE 273
#define EPSV 1e-12f
#define C2F 0.17677669529663688f  // 1/(4*sqrt(2))

// ----- scratch (static device allocations; no cudaMalloc allowed) -----
__device__ float gQK[8192 * 512];      // [m][h*16+f] Q at col 0..255, K at 256..511
__device__ float gV[8192 * 1024];
__device__ float gS[1024 * DE * 64];   // [bh*16+c][273][64]
__device__ float gZ[1024 * DE];        // [bh*16+c][273]
__device__ __nv_bfloat16 gHh[8192 * 1024];
__device__ __nv_bfloat16 gHl[8192 * 1024];
__device__ __nv_bfloat16 gWh[1024 * 1024];
__device__ __nv_bfloat16 gWl[1024 * 1024];
__device__ __nv_bfloat16 gYh[8192 * 1024];
__device__ __nv_bfloat16 gYl[8192 * 1024];

// ============================================================================
// helpers (portable PTX only: cp.async / ldmatrix / mma.sync)
// ============================================================================
__device__ __forceinline__ uint32_t smem_u32(const void* p) {
    uint32_t a;
    asm("{ .reg .u64 t; cvta.to.shared.u64 t, %1; cvt.u32.u64 %0, t; }" : "=r"(a) : "l"(p));
    return a;
}
__device__ __forceinline__ void cpasync16(uint32_t dst, const void* src) {
    asm volatile("cp.async.cg.shared.global [%0], [%1], 16;" :: "r"(dst), "l"(src));
}
__device__ __forceinline__ void cpasync_commit() {
    asm volatile("cp.async.commit_group;" ::: "memory");
}
__device__ __forceinline__ void cpasync_wait_all() {
    asm volatile("cp.async.wait_group 0;" ::: "memory");
}
__device__ __forceinline__ void ldsm4(uint32_t* r, uint32_t addr) {
    asm volatile("ldmatrix.sync.aligned.m8n8.x4.shared.b16 {%0,%1,%2,%3}, [%4];"
        : "=r"(r[0]), "=r"(r[1]), "=r"(r[2]), "=r"(r[3]) : "r"(addr));
}
__device__ __forceinline__ void mma_bf16(float* d, const uint32_t* a, const uint32_t* b) {
    asm volatile(
        "mma.sync.aligned.m16n8k16.row.col.f32.bf16.bf16.f32 "
        "{%0,%1,%2,%3}, {%4,%5,%6,%7}, {%8,%9}, {%0,%1,%2,%3};"
        : "+f"(d[0]), "+f"(d[1]), "+f"(d[2]), "+f"(d[3])
        : "r"(a[0]), "r"(a[1]), "r"(a[2]), "r"(a[3]), "r"(b[0]), "r"(b[1]));
}
__device__ __forceinline__ uint32_t sw128(uint32_t bo) { return bo ^ ((bo >> 3) & 0x70); }

// ============================================================================
// fp32 -> (hi, lo) bf16 split conversion.  one block = 1024 elements.
// ============================================================================
__global__ void __launch_bounds__(256) cvt_hilo(
    const float* __restrict__ src, __nv_bfloat16* __restrict__ hi,
    __nv_bfloat16* __restrict__ lo)
{
    int i = (blockIdx.x * 256 + threadIdx.x) * 4;
    float4 v = *(const float4*)(src + i);
    __nv_bfloat16 h0 = __float2bfloat16(v.x), h1 = __float2bfloat16(v.y);
    __nv_bfloat16 h2 = __float2bfloat16(v.z), h3 = __float2bfloat16(v.w);
    __nv_bfloat16 l0 = __float2bfloat16(v.x - __bfloat162float(h0));
    __nv_bfloat16 l1 = __float2bfloat16(v.y - __bfloat162float(h1));
    __nv_bfloat16 l2 = __float2bfloat16(v.z - __bfloat162float(h2));
    __nv_bfloat16 l3 = __float2bfloat16(v.w - __bfloat162float(h3));
    __nv_bfloat162* ph = (__nv_bfloat162*)(hi + i);
    __nv_bfloat162* pl = (__nv_bfloat162*)(lo + i);
    ph[0] = __nv_bfloat162(h0, h1); ph[1] = __nv_bfloat162(h2, h3);
    pl[0] = __nv_bfloat162(l0, l1); pl[1] = __nv_bfloat162(l2, l3);
}

// ============================================================================
// split-bf16 HMMA GEMM (NT): unchanged from R4 (validated).
// ============================================================================
__global__ void __launch_bounds__(256) gemm_mma(
    const __nv_bfloat16* __restrict__ Ah, const __nv_bfloat16* __restrict__ Al,
    const __nv_bfloat16* __restrict__ Bh, const __nv_bfloat16* __restrict__ Bl,
    float* __restrict__ C, int N, int K)
{
    extern __shared__ char smem[];
    const uint32_t sb = smem_u32(smem);
    const int tid = threadIdx.x, wid = tid >> 5, l = tid & 31;
    const int wm = wid & 3, wn = wid >> 2;
    const int bm = blockIdx.y * 128, bn = blockIdx.x * 128;

    const __nv_bfloat16* gp0[4] = {
        Ah + (size_t)bm * K, Al + (size_t)bm * K,
        Bh + (size_t)bn * K, Bl + (size_t)bn * K };

    const int NST = K >> 6;

    float acc[2][8][4];
#pragma unroll
    for (int mt = 0; mt < 2; ++mt)
#pragma unroll
        for (int nt = 0; nt < 8; ++nt)
#pragma unroll
            for (int c = 0; c < 4; ++c) acc[mt][nt][c] = 0.f;

    {
        const uint32_t sdst = sb;
#pragma unroll
        for (int t = 0; t < 4; ++t)
#pragma unroll
            for (int it = 0; it < 4; ++it) {
                int ch = tid + it * 256;
                int row = ch >> 3, cb = ch & 7;
                cpasync16(sdst + t * 16384 + sw128(row * 128 + cb * 16),
                          gp0[t] + (size_t)row * K + cb * 8);
            }
        cpasync_commit();
    }

    for (int s = 0; s < NST; ++s) {
        cpasync_wait_all();
        __syncthreads();
        if (s + 1 < NST) {
            const uint32_t sdst = sb + (uint32_t)((s + 1) & 1) * 65536u;
            const int k0 = (s + 1) * 64;
#pragma unroll
            for (int t = 0; t < 4; ++t)
#pragma unroll
                for (int it = 0; it < 4; ++it) {
                    int ch = tid + it * 256;
                    int row = ch >> 3, cb = ch & 7;
                    cpasync16(sdst + t * 16384 + sw128(row * 128 + cb * 16),
                              gp0[t] + (size_t)row * K + k0 + cb * 8);
                }
            cpasync_commit();
        }
        const uint32_t sc = sb + (uint32_t)(s & 1) * 65536u;
#pragma unroll
        for (int ks = 0; ks < 4; ++ks) {
            uint32_t ah[2][4], al[2][4], bh[8][2], bl[8][2];
#pragma unroll
            for (int mt = 0; mt < 2; ++mt) {
                uint32_t bo = (uint32_t)(wm * 32 + mt * 16 + (l & 15)) * 128
                            + ks * 32 + ((l >> 4) << 4);
                bo = sw128(bo);
                ldsm4(ah[mt], sc + bo);
                ldsm4(al[mt], sc + 16384 + bo);
            }
#pragma unroll
            for (int p = 0; p < 4; ++p) {
                uint32_t n = (uint32_t)(wn * 64 + p * 16 + (l & 7) + ((l >> 4) << 3));
                uint32_t bo = n * 128 + ks * 32 + (((l >> 3) & 1) << 4);
                bo = sw128(bo);
                uint32_t r[4];
                ldsm4(r, sc + 32768 + bo);
                bh[2 * p][0] = r[0]; bh[2 * p][1] = r[1];
                bh[2 * p + 1][0] = r[2]; bh[2 * p + 1][1] = r[3];
                ldsm4(r, sc + 49152 + bo);
                bl[2 * p][0] = r[0]; bl[2 * p][1] = r[1];
                bl[2 * p + 1][0] = r[2]; bl[2 * p + 1][1] = r[3];
            }
#pragma unroll
            for (int mt = 0; mt < 2; ++mt)
#pragma unroll
                for (int nt = 0; nt < 8; ++nt) mma_bf16(acc[mt][nt], ah[mt], bh[nt]);
#pragma unroll
            for (int mt = 0; mt < 2; ++mt)
#pragma unroll
                for (int nt = 0; nt < 8; ++nt) mma_bf16(acc[mt][nt], ah[mt], bl[nt]);
#pragma unroll
            for (int mt = 0; mt < 2; ++mt)
#pragma unroll
                for (int nt = 0; nt < 8; ++nt) mma_bf16(acc[mt][nt], al[mt], bh[nt]);
        }
        __syncthreads();
    }

    const int r0 = bm + wm * 32 + (l >> 2);
    const int c0 = bn + wn * 64 + 2 * (l & 3);
#pragma unroll
    for (int mt = 0; mt < 2; ++mt)
#pragma unroll
        for (int nt = 0; nt < 8; ++nt) {
            float* p0 = C + (size_t)(r0 + mt * 16) * N + c0 + nt * 8;
            float* p1 = C + (size_t)(r0 + mt * 16 + 8) * N + c0 + nt * 8;
            *(float2*)p0 = make_float2(acc[mt][nt][0], acc[mt][nt][1]);
            *(float2*)p1 = make_float2(acc[mt][nt][2], acc[mt][nt][3]);
        }
}

// ============================================================================
// Phase A (MMA): per-(bh,c) S_c = kf^T @ v and z_c via ones-column.
// A = kfT [288][128] hi/lo (row stride 136 elems = 272B, conflict-free ldsm)
// B = vT  [80][128]  hi/lo (row 64 = ones, 65..79 = 0), N = 72 used.
// SMEM = 200192 B, 256 threads, 1 CTA/SM.
// ============================================================================
#define LDA_A 136
__global__ void __launch_bounds__(256, 1) chunk_state_mma()
{
    extern __shared__ char smraw[];
    __nv_bfloat16* sKh = (__nv_bfloat16*)smraw;       // 288*136
    __nv_bfloat16* sKl = sKh + 288 * LDA_A;
    __nv_bfloat16* sVh = sKl + 288 * LDA_A;           // 80*136
    __nv_bfloat16* sVl = sVh + 80 * LDA_A;

    const int bid = blockIdx.x;
    const int bh = bid >> 4, c = bid & 15;
    const int b = bh >> 4, h = bh & 15;
    const int tid = threadIdx.x, wid = tid >> 5, l = tid & 31;
    const int m0 = b * 2048 + c * 128;

    // ---- build kf^T (hi/lo) ----
    {
        const int j = tid >> 1, half = tid & 1;
        const float* kp = gQK + (size_t)(m0 + j) * 512 + 256 + h * 16;
        float kr[16];
#pragma unroll
        for (int f = 0; f < 16; f += 4) {
            float4 v4 = *(const float4*)(kp + f);
            kr[f] = v4.x; kr[f + 1] = v4.y; kr[f + 2] = v4.z; kr[f + 3] = v4.w;
        }
        for (int dd = 0; dd < 144; ++dd) {
            int d = half * 144 + dd;
            float val;
            if (d == 0) val = 1.f;
            else if (d < 17) val = kr[d - 1] * 0.5f;
            else if (d < 273) { int t = d - 17; val = kr[t >> 4] * kr[t & 15] * C2F; }
            else val = 0.f;
            __nv_bfloat16 hv = __float2bfloat16(val);
            sKh[d * LDA_A + j] = hv;
            sKl[d * LDA_A + j] = __float2bfloat16(val - __bfloat162float(hv));
        }
    }
    // ---- build v^T (hi/lo) + ones row 64 + zero rows 65..79 ----
    for (int idx = tid; idx < 8192; idx += 256) {
        int j = idx >> 6, e = idx & 63;
        float v = gV[(size_t)(m0 + j) * 1024 + h * 64 + e];
        __nv_bfloat16 hv = __float2bfloat16(v);
        sVh[e * LDA_A + j] = hv;
        sVl[e * LDA_A + j] = __float2bfloat16(v - __bfloat162float(hv));
    }
    for (int idx = tid; idx < 16 * 128; idx += 256) {
        int e = 64 + (idx >> 7), j = idx & 127;
        sVh[e * LDA_A + j] = __float2bfloat16(e == 64 ? 1.f : 0.f);
        sVl[e * LDA_A + j] = __float2bfloat16(0.f);
    }
    __syncthreads();

    // ---- MMA: M=288 (18 m-frags over 8 warps), N=72 (9 n-frags), K=128 ----
    const uint32_t aKh = smem_u32(sKh), aKl = smem_u32(sKl);
    const uint32_t aVh = smem_u32(sVh), aVl = smem_u32(sVl);
    const int nmf = (wid < 2) ? 3 : 2;

    float acc[3][9][4];
#pragma unroll
    for (int r = 0; r < 3; ++r)
#pragma unroll
        for (int nf = 0; nf < 9; ++nf)
#pragma unroll
            for (int cc = 0; cc < 4; ++cc) acc[r][nf][cc] = 0.f;

    for (int ks = 0; ks < 8; ++ks) {
        uint32_t ah[3][4], al[3][4];
#pragma unroll
        for (int r = 0; r < 3; ++r) if (r < nmf) {
            int mf = wid + 8 * r;
            uint32_t bo = (uint32_t)(mf * 16 + (l & 15)) * (LDA_A * 2)
                        + ks * 32 + ((l >> 4) << 4);
            ldsm4(ah[r], aKh + bo);
            ldsm4(al[r], aKl + bo);
        }
        uint32_t bhf[10][2], blf[10][2];
#pragma unroll
        for (int p = 0; p < 5; ++p) {
            uint32_t n = (uint32_t)(p * 16 + (l & 7) + ((l >> 4) << 3));
            uint32_t bo = n * (LDA_A * 2) + ks * 32 + (((l >> 3) & 1) << 4);
            uint32_t r4[4];
            ldsm4(r4, aVh + bo);
            bhf[2 * p][0] = r4[0]; bhf[2 * p][1] = r4[1];
            bhf[2 * p + 1][0] = r4[2]; bhf[2 * p + 1][1] = r4[3];
            ldsm4(r4, aVl + bo);
            blf[2 * p][0] = r4[0]; blf[2 * p][1] = r4[1];
            blf[2 * p + 1][0] = r4[2]; blf[2 * p + 1][1] = r4[3];
        }
#pragma unroll
        for (int r = 0; r < 3; ++r) if (r < nmf)
#pragma unroll
            for (int nf = 0; nf < 9; ++nf) {
                mma_bf16(acc[r][nf], ah[r], bhf[nf]);
                mma_bf16(acc[r][nf], ah[r], blf[nf]);
                mma_bf16(acc[r][nf], al[r], bhf[nf]);
            }
    }

    // ---- writeback S (cols 0..63) and z (col 64) ----
    float* outS = gS + (size_t)bid * (DE * 64);
    float* outZ = gZ + (size_t)bid * DE;
#pragma unroll
    for (int r = 0; r < 3; ++r) if (r < nmf) {
        int mf = wid + 8 * r;
        int d0r = mf * 16 + (l >> 2);
#pragma unroll
        for (int nf = 0; nf < 9; ++nf) {
            int c0 = nf * 8 + 2 * (l & 3);
#pragma unroll
            for (int hh = 0; hh < 2; ++hh) {
                int d = d0r + hh * 8;
                if (d < DE) {
                    if (c0 < 64) {
                        outS[d * 64 + c0] = acc[r][nf][hh * 2];
                        outS[d * 64 + c0 + 1] = acc[r][nf][hh * 2 + 1];
                    } else if (c0 == 64) {
                        outZ[d] = acc[r][nf][hh * 2];
                    }
                }
            }
        }
    }
}

// ============================================================================
// Phase B: exclusive prefix over 16 chunks per (b,h)
// ============================================================================
__global__ void __launch_bounds__(256) prefix_kernel()
{
    const int bh = blockIdx.x;
    float* Sb = gS + (size_t)bh * 16 * (DE * 64);
    for (int idx = threadIdx.x; idx < DE * 64; idx += 256) {
        float run = 0.f;
#pragma unroll
        for (int c = 0; c < 16; ++c) {
            float* p = Sb + c * (DE * 64) + idx;
            float tmp = *p;
            *p = run;
            run += tmp;
        }
    }
    float* Zb = gZ + (size_t)bh * 16 * DE;
    for (int idx = threadIdx.x; idx < DE; idx += 256) {
        float run = 0.f;
#pragma unroll
        for (int c = 0; c < 16; ++c) {
            float* p = Zb + c * DE + idx;
            float tmp = *p;
            *p = run;
            run += tmp;
        }
    }
}

// ============================================================================
// Phase C (MMA): per-(bh,c) output.
//  step1 (SIMT): attn = mask*poly(q.k) -> sA hi/lo
//  step2 (MMA):  acc += attn @ [vT | ones]          (K=128, N=72)
//  step3 (MMA):  acc += qf @ [S^T | z], 2 d-tiles   (K=144 each)
//  y = accY / (accD + eps) -> gYh/gYl
// A rows stride 152 elems (304B), B rows stride 152.  SMEM 143872 B.
// ============================================================================
#define LDA_C 152
__global__ void __launch_bounds__(256, 1) chunk_out_mma()
{
    extern __shared__ char smraw[];
    __nv_bfloat16* sAh = (__nv_bfloat16*)smraw;        // 128*152
    __nv_bfloat16* sAl = sAh + 128 * LDA_C;
    __nv_bfloat16* sBh = sAl + 128 * LDA_C;            // 80*152
    __nv_bfloat16* sBl = sBh + 80 * LDA_C;
    float* sQ = (float*)(sBl + 80 * LDA_C);            // 128*17
    float* sK = sQ + 128 * 17;                          // 128*17

    const int bid = blockIdx.x;
    const int bh = bid >> 4, c = bid & 15;
    const int b = bh >> 4, h = bh & 15;
    const int tid = threadIdx.x, wid = tid >> 5, l = tid & 31;
    const int m0 = b * 2048 + c * 128;

    // ---- load q,k fp32 ----
    for (int idx = tid; idx < 2048; idx += 256) {
        int i = idx >> 4, f = idx & 15;
        sQ[i * 17 + f] = gQK[(size_t)(m0 + i) * 512 + h * 16 + f];
        sK[i * 17 + f] = gQK[(size_t)(m0 + i) * 512 + 256 + h * 16 + f];
    }
    __syncthreads();

    // ---- step1: attn (masked poly) -> sA hi/lo ----
    for (int idx = tid; idx < 16384; idx += 256) {
        int i = idx >> 7, j = idx & 127;
        float dot = 0.f;
#pragma unroll
        for (int f = 0; f < 16; ++f) dot += sQ[i * 17 + f] * sK[j * 17 + f];
        float a = 1.f + dot * 0.25f + dot * dot * 0.03125f;
        a = (j <= i) ? a : 0.f;
        __nv_bfloat16 hv = __float2bfloat16(a);
        sAh[i * LDA_C + j] = hv;
        sAl[i * LDA_C + j] = __float2bfloat16(a - __bfloat162float(hv));
    }
    // ---- vT + ones row 64 + zero rows 65..79 ----
    for (int idx = tid; idx < 8192; idx += 256) {
        int j = idx >> 6, e = idx & 63;
        float v = gV[(size_t)(m0 + j) * 1024 + h * 64 + e];
        __nv_bfloat16 hv = __float2bfloat16(v);
        sBh[e * LDA_C + j] = hv;
        sBl[e * LDA_C + j] = __float2bfloat16(v - __bfloat162float(hv));
    }
    for (int idx = tid; idx < 16 * 144; idx += 256) {
        int e = 64 + (idx / 144), j = idx % 144;
        sBh[e * LDA_C + j] = __float2bfloat16(e == 64 ? 1.f : 0.f);
        sBl[e * LDA_C + j] = __float2bfloat16(0.f);
    }
    __syncthreads();

    const uint32_t aAh = smem_u32(sAh), aAl = smem_u32(sAl);
    const uint32_t aBh = smem_u32(sBh), aBl = smem_u32(sBl);

    float acc[9][4];
#pragma unroll
    for (int nf = 0; nf < 9; ++nf)
#pragma unroll
        for (int cc = 0; cc < 4; ++cc) acc[nf][cc] = 0.f;

    // ---- step2: intra-chunk MMA (K=128) ----
    for (int ks = 0; ks < 8; ++ks) {
        uint32_t ah[4], al[4];
        {
            uint32_t bo = (uint32_t)(wid * 16 + (l & 15)) * (LDA_C * 2)
                        + ks * 32 + ((l >> 4) << 4);
            ldsm4(ah, aAh + bo);
            ldsm4(al, aAl + bo);
        }
        uint32_t bhf[10][2], blf[10][2];
#pragma unroll
        for (int p = 0; p < 5; ++p) {
            uint32_t n = (uint32_t)(p * 16 + (l & 7) + ((l >> 4) << 3));
            uint32_t bo = n * (LDA_C * 2) + ks * 32 + (((l >> 3) & 1) << 4);
            uint32_t r4[4];
            ldsm4(r4, aBh + bo);
            bhf[2 * p][0] = r4[0]; bhf[2 * p][1] = r4[1];
            bhf[2 * p + 1][0] = r4[2]; bhf[2 * p + 1][1] = r4[3];
            ldsm4(r4, aBl + bo);
            blf[2 * p][0] = r4[0]; blf[2 * p][1] = r4[1];
            blf[2 * p + 1][0] = r4[2]; blf[2 * p + 1][1] = r4[3];
        }
#pragma unroll
        for (int nf = 0; nf < 9; ++nf) {
            mma_bf16(acc[nf], ah, bhf[nf]);
            mma_bf16(acc[nf], ah, blf[nf]);
            mma_bf16(acc[nf], al, bhf[nf]);
        }
    }
    __syncthreads();

    // ---- step3: inter-chunk, 2 d-tiles of 144 ----
    const float* Sp = gS + (size_t)bid * (DE * 64);
    const float* Zp = gZ + (size_t)bid * DE;
    for (int dt = 0; dt < 2; ++dt) {
        const int d0 = dt * 144;
        // qf tile -> sA
        {
            const int i = tid >> 1, half = tid & 1;
            const float* qp = sQ + i * 17;
            for (int dd = 0; dd < 72; ++dd) {
                int dloc = half * 72 + dd;
                int d = d0 + dloc;
                float val;
                if (d == 0) val = 1.f;
                else if (d < 17) val = qp[d - 1] * 0.5f;
                else if (d < 273) { int t = d - 17; val = qp[t >> 4] * qp[t & 15] * C2F; }
                else val = 0.f;
                __nv_bfloat16 hv = __float2bfloat16(val);
                sAh[i * LDA_C + dloc] = hv;
                sAl[i * LDA_C + dloc] = __float2bfloat16(val - __bfloat162float(hv));
            }
        }
        // S^T tile + z row -> sB (rows 65..79 stay zero)
        for (int idx = tid; idx < 144 * 64; idx += 256) {
            int dd = idx >> 6, e = idx & 63;
            int d = d0 + dd;
            float v = (d < DE) ? Sp[d * 64 + e] : 0.f;
            __nv_bfloat16 hv = __float2bfloat16(v);
            sBh[e * LDA_C + dd] = hv;
            sBl[e * LDA_C + dd] = __float2bfloat16(v - __bfloat162float(hv));
        }
        for (int idx = tid; idx < 144; idx += 256) {
            int d = d0 + idx;
            float v = (d < DE) ? Zp[d] : 0.f;
            __nv_bfloat16 hv = __float2bfloat16(v);
            sBh[64 * LDA_C + idx] = hv;
            sBl[64 * LDA_C + idx] = __float2bfloat16(v - __bfloat162float(hv));
        }
        __syncthreads();

        for (int ks = 0; ks < 9; ++ks) {
            uint32_t ah[4], al[4];
            {
                uint32_t bo = (uint32_t)(wid * 16 + (l & 15)) * (LDA_C * 2)
                            + ks * 32 + ((l >> 4) << 4);
                ldsm4(ah, aAh + bo);
                ldsm4(al, aAl + bo);
            }
            uint32_t bhf[10][2], blf[10][2];
#pragma unroll
            for (int p = 0; p < 5; ++p) {
                uint32_t n = (uint32_t)(p * 16 + (l & 7) + ((l >> 4) << 3));
                uint32_t bo = n * (LDA_C * 2) + ks * 32 + (((l >> 3) & 1) << 4);
                uint32_t r4[4];
                ldsm4(r4, aBh + bo);
                bhf[2 * p][0] = r4[0]; bhf[2 * p][1] = r4[1];
                bhf[2 * p + 1][0] = r4[2]; bhf[2 * p + 1][1] = r4[3];
                ldsm4(r4, aBl + bo);
                blf[2 * p][0] = r4[0]; blf[2 * p][1] = r4[1];
                blf[2 * p + 1][0] = r4[2]; blf[2 * p + 1][1] = r4[3];
            }
#pragma unroll
            for (int nf = 0; nf < 9; ++nf) {
                mma_bf16(acc[nf], ah, bhf[nf]);
                mma_bf16(acc[nf], ah, blf[nf]);
                mma_bf16(acc[nf], al, bhf[nf]);
            }
        }
        __syncthreads();
    }

    // ---- divide + store y (bf16 hi/lo) ----
    float den0 = __shfl_sync(0xffffffffu, acc[8][0], l & 28);
    float den1 = __shfl_sync(0xffffffffu, acc[8][2], l & 28);
    float inv0 = 1.f / (den0 + EPSV);
    float inv1 = 1.f / (den1 + EPSV);
    const int r0 = wid * 16 + (l >> 2);
#pragma unroll
    for (int nf = 0; nf < 8; ++nf) {
        int c0 = nf * 8 + 2 * (l & 3);
#pragma unroll
        for (int hh = 0; hh < 2; ++hh) {
            int row = r0 + hh * 8;
            float inv = hh ? inv1 : inv0;
            size_t base = (size_t)(m0 + row) * 1024 + h * 64 + c0;
#pragma unroll
            for (int cc = 0; cc < 2; ++cc) {
                float yv = acc[nf][hh * 2 + cc] * inv;
                __nv_bfloat16 hv = __float2bfloat16(yv);
                gYh[base + cc] = hv;
                gYl[base + cc] = __float2bfloat16(yv - __bfloat162float(hv));
            }
        }
    }
}

// ============================================================================
// host launch
// ============================================================================
extern "C" void kernel_launch(void* const* d_in, const int* in_sizes, int n_in,
                              void* d_out, int out_size)
{
    const float* hs = (const float*)d_in[0];
    const float* Wq = (const float*)d_in[1];
    const float* Wk = (const float*)d_in[2];
    const float* Wv = (const float*)d_in[3];
    const float* Wo = (const float*)d_in[4];
    float* out = (float*)d_out;

    float *pQK, *pV;
    __nv_bfloat16 *pHh, *pHl, *pWh, *pWl, *pYh, *pYl;
    cudaGetSymbolAddress((void**)&pQK, gQK);
    cudaGetSymbolAddress((void**)&pV, gV);
    cudaGetSymbolAddress((void**)&pHh, gHh);
    cudaGetSymbolAddress((void**)&pHl, gHl);
    cudaGetSymbolAddress((void**)&pWh, gWh);
    cudaGetSymbolAddress((void**)&pWl, gWl);
    cudaGetSymbolAddress((void**)&pYh, gYh);
    cudaGetSymbolAddress((void**)&pYl, gYl);

    const int SMEM_G  = 131072;   // 2 x 64KB stages
    const int SMEM_CS = (2 * 288 * LDA_A + 2 * 80 * LDA_A) * 2;          // 200192
    const int SMEM_CO = (2 * 128 * LDA_C + 2 * 80 * LDA_C) * 2 + 2 * 128 * 17 * 4; // 143872
    cudaFuncSetAttribute(gemm_mma,
                         cudaFuncAttributeMaxDynamicSharedMemorySize, SMEM_G);
    cudaFuncSetAttribute(chunk_state_mma,
                         cudaFuncAttributeMaxDynamicSharedMemorySize, SMEM_CS);
    cudaFuncSetAttribute(chunk_out_mma,
                         cudaFuncAttributeMaxDynamicSharedMemorySize, SMEM_CO);

    dim3 blk(256);
    // hidden -> hi/lo bf16
    cvt_hilo<<<8192, blk>>>(hs, pHh, pHl);

    // fused Q|K projection (N = 512)
    cvt_hilo<<<256, blk>>>(Wq, pWh, pWl);
    cvt_hilo<<<256, blk>>>(Wk, pWh + 256 * 1024, pWl + 256 * 1024);
    gemm_mma<<<dim3(4, 64), blk, SMEM_G>>>(pHh, pHl, pWh, pWl, pQK, 512, 1024);

    // V projection
    cvt_hilo<<<1024, blk>>>(Wv, pWh, pWl);
    gemm_mma<<<dim3(8, 64), blk, SMEM_G>>>(pHh, pHl, pWh, pWl, pV, 1024, 1024);

    // chunked linear attention (MMA phases)
    chunk_state_mma<<<1024, blk, SMEM_CS>>>();
    prefix_kernel<<<64, blk>>>();
    chunk_out_mma<<<1024, blk, SMEM_CO>>>();

    // output projection
    cvt_hilo<<<1024, blk>>>(Wo, pWh, pWl);
    gemm_mma<<<dim3(8, 64), blk, SMEM_G>>>(pYh, pYl, pWh, pWl, out, 1024, 1024);
}

// round 6
// speedup vs baseline: 2.2696x; 1.0757x over previous
#include <cuda_runtime.h>
#include <cuda_bf16.h>
#include <cstdint>

#define DE 273
#define EPSV 1e-12f
#define C2F 0.17677669529663688f  // 1/(4*sqrt(2))

// ----- scratch (static device allocations; no cudaMalloc allowed) -----
__device__ float gQK[8192 * 512];      // [m][h*16+f] Q at col 0..255, K at 256..511
__device__ float gV[8192 * 1024];
__device__ float gS[1024 * DE * 64];   // [bh*16+c][273][64]
__device__ float gZ[1024 * DE];        // [bh*16+c][273]
__device__ __nv_bfloat16 gHh[8192 * 1024];
__device__ __nv_bfloat16 gHl[8192 * 1024];
__device__ __nv_bfloat16 gWh[1024 * 1024];
__device__ __nv_bfloat16 gWl[1024 * 1024];
__device__ __nv_bfloat16 gYh[8192 * 1024];
__device__ __nv_bfloat16 gYl[8192 * 1024];

// ============================================================================
// helpers (portable PTX only: cp.async / ldmatrix / mma.sync)
// ============================================================================
__device__ __forceinline__ uint32_t smem_u32(const void* p) {
    uint32_t a;
    asm("{ .reg .u64 t; cvta.to.shared.u64 t, %1; cvt.u32.u64 %0, t; }" : "=r"(a) : "l"(p));
    return a;
}
__device__ __forceinline__ void cpasync16(uint32_t dst, const void* src) {
    asm volatile("cp.async.cg.shared.global [%0], [%1], 16;" :: "r"(dst), "l"(src));
}
__device__ __forceinline__ void cpasync_commit() {
    asm volatile("cp.async.commit_group;" ::: "memory");
}
__device__ __forceinline__ void cpasync_wait0() {
    asm volatile("cp.async.wait_group 0;" ::: "memory");
}
__device__ __forceinline__ void cpasync_wait1() {
    asm volatile("cp.async.wait_group 1;" ::: "memory");
}
__device__ __forceinline__ void ldsm4(uint32_t* r, uint32_t addr) {
    asm volatile("ldmatrix.sync.aligned.m8n8.x4.shared.b16 {%0,%1,%2,%3}, [%4];"
        : "=r"(r[0]), "=r"(r[1]), "=r"(r[2]), "=r"(r[3]) : "r"(addr));
}
__device__ __forceinline__ void mma_bf16(float* d, const uint32_t* a, const uint32_t* b) {
    asm volatile(
        "mma.sync.aligned.m16n8k16.row.col.f32.bf16.bf16.f32 "
        "{%0,%1,%2,%3}, {%4,%5,%6,%7}, {%8,%9}, {%0,%1,%2,%3};"
        : "+f"(d[0]), "+f"(d[1]), "+f"(d[2]), "+f"(d[3])
        : "r"(a[0]), "r"(a[1]), "r"(a[2]), "r"(a[3]), "r"(b[0]), "r"(b[1]));
}
__device__ __forceinline__ uint32_t sw64(uint32_t bo) { return bo ^ ((bo >> 3) & 0x30); }
__device__ __forceinline__ uint32_t hipack(float x, float y) {
    __nv_bfloat162 h(__float2bfloat16(x), __float2bfloat16(y));
    return *(uint32_t*)&h;
}
__device__ __forceinline__ uint32_t lopack(float x, float y) {
    float xr = x - __bfloat162float(__float2bfloat16(x));
    float yr = y - __bfloat162float(__float2bfloat16(y));
    __nv_bfloat162 h(__float2bfloat16(xr), __float2bfloat16(yr));
    return *(uint32_t*)&h;
}

// ============================================================================
// fp32 -> (hi, lo) bf16 split conversion.  one block = 1024 elements.
// ============================================================================
__global__ void __launch_bounds__(256) cvt_hilo(
    const float* __restrict__ src, __nv_bfloat16* __restrict__ hi,
    __nv_bfloat16* __restrict__ lo)
{
    int i = (blockIdx.x * 256 + threadIdx.x) * 4;
    float4 v = *(const float4*)(src + i);
    __nv_bfloat16 h0 = __float2bfloat16(v.x), h1 = __float2bfloat16(v.y);
    __nv_bfloat16 h2 = __float2bfloat16(v.z), h3 = __float2bfloat16(v.w);
    __nv_bfloat16 l0 = __float2bfloat16(v.x - __bfloat162float(h0));
    __nv_bfloat16 l1 = __float2bfloat16(v.y - __bfloat162float(h1));
    __nv_bfloat16 l2 = __float2bfloat16(v.z - __bfloat162float(h2));
    __nv_bfloat16 l3 = __float2bfloat16(v.w - __bfloat162float(h3));
    __nv_bfloat162* ph = (__nv_bfloat162*)(hi + i);
    __nv_bfloat162* pl = (__nv_bfloat162*)(lo + i);
    ph[0] = __nv_bfloat162(h0, h1); ph[1] = __nv_bfloat162(h2, h3);
    pl[0] = __nv_bfloat162(l0, l1); pl[1] = __nv_bfloat162(l2, l3);
}

// ============================================================================
// split-bf16 HMMA GEMM (NT): C = Ah*Bh + Ah*Bl + Al*Bh, fp32-quality.
// CTA tile 128x128, K in stages of 32, 3-stage cp.async pipeline,
// SW64-swizzled 64B rows, 2 CTAs/SM (96KB smem, <=128 regs target).
// ============================================================================
__device__ __forceinline__ void g_issue(uint32_t sb, int s,
    const __nv_bfloat16* __restrict__ pAh, const __nv_bfloat16* __restrict__ pAl,
    const __nv_bfloat16* __restrict__ pBh, const __nv_bfloat16* __restrict__ pBl,
    int K, int tid)
{
    const uint32_t dst = sb + (uint32_t)(s % 3) * 32768u;
    const int k0 = s * 32;
#pragma unroll
    for (int it = 0; it < 2; ++it) {
        int ch = tid + it * 256;
        int row = ch >> 2, cb = ch & 3;
        uint32_t so = sw64((uint32_t)(row * 64 + cb * 16));
        size_t go = (size_t)row * K + k0 + cb * 8;
        cpasync16(dst + so,         pAh + go);
        cpasync16(dst + 8192 + so,  pAl + go);
        cpasync16(dst + 16384 + so, pBh + go);
        cpasync16(dst + 24576 + so, pBl + go);
    }
    cpasync_commit();
}

__global__ void __launch_bounds__(256, 2) gemm_mma(
    const __nv_bfloat16* __restrict__ Ah, const __nv_bfloat16* __restrict__ Al,
    const __nv_bfloat16* __restrict__ Bh, const __nv_bfloat16* __restrict__ Bl,
    float* __restrict__ C, int N, int K)
{
    extern __shared__ char smem[];
    const uint32_t sb = smem_u32(smem);
    const int tid = threadIdx.x, wid = tid >> 5, l = tid & 31;
    const int wm = wid & 3, wn = wid >> 2;
    const int bm = blockIdx.y * 128, bn = blockIdx.x * 128;

    const __nv_bfloat16* pAh = Ah + (size_t)bm * K;
    const __nv_bfloat16* pAl = Al + (size_t)bm * K;
    const __nv_bfloat16* pBh = Bh + (size_t)bn * K;
    const __nv_bfloat16* pBl = Bl + (size_t)bn * K;

    const int NST = K >> 5;

    float acc[2][8][4];
#pragma unroll
    for (int mt = 0; mt < 2; ++mt)
#pragma unroll
        for (int nt = 0; nt < 8; ++nt)
#pragma unroll
            for (int c = 0; c < 4; ++c) acc[mt][nt][c] = 0.f;

    g_issue(sb, 0, pAh, pAl, pBh, pBl, K, tid);
    g_issue(sb, 1, pAh, pAl, pBh, pBl, K, tid);

    for (int s = 0; s < NST; ++s) {
        if (s + 2 < NST) {
            cpasync_wait1();
            __syncthreads();
            g_issue(sb, s + 2, pAh, pAl, pBh, pBl, K, tid);
        } else {
            cpasync_wait0();
            __syncthreads();
        }
        const uint32_t sc = sb + (uint32_t)(s % 3) * 32768u;
#pragma unroll
        for (int ks2 = 0; ks2 < 2; ++ks2) {
            uint32_t ah[2][4], al[2][4];
#pragma unroll
            for (int mt = 0; mt < 2; ++mt) {
                uint32_t bo = sw64((uint32_t)((wm * 32 + mt * 16 + (l & 15)) * 64
                                   + ks2 * 32 + ((l >> 4) << 4)));
                ldsm4(ah[mt], sc + bo);
                ldsm4(al[mt], sc + 8192 + bo);
            }
#pragma unroll
            for (int p = 0; p < 4; ++p) {
                uint32_t n = (uint32_t)(wn * 64 + p * 16 + (l & 7) + ((l >> 4) << 3));
                uint32_t bo = sw64(n * 64 + ks2 * 32 + (((l >> 3) & 1) << 4));
                uint32_t rb[4], rl[4];
                ldsm4(rb, sc + 16384 + bo);
                ldsm4(rl, sc + 24576 + bo);
                uint32_t b0[2] = {rb[0], rb[1]}, b1[2] = {rb[2], rb[3]};
                uint32_t c0[2] = {rl[0], rl[1]}, c1[2] = {rl[2], rl[3]};
#pragma unroll
                for (int mt = 0; mt < 2; ++mt) {
                    mma_bf16(acc[mt][2 * p],     ah[mt], b0);
                    mma_bf16(acc[mt][2 * p + 1], ah[mt], b1);
                    mma_bf16(acc[mt][2 * p],     ah[mt], c0);
                    mma_bf16(acc[mt][2 * p + 1], ah[mt], c1);
                    mma_bf16(acc[mt][2 * p],     al[mt], b0);
                    mma_bf16(acc[mt][2 * p + 1], al[mt], b1);
                }
            }
        }
        __syncthreads();
    }

    const int r0 = bm + wm * 32 + (l >> 2);
    const int c0 = bn + wn * 64 + 2 * (l & 3);
#pragma unroll
    for (int mt = 0; mt < 2; ++mt)
#pragma unroll
        for (int nt = 0; nt < 8; ++nt) {
            float* p0 = C + (size_t)(r0 + mt * 16) * N + c0 + nt * 8;
            float* p1 = C + (size_t)(r0 + mt * 16 + 8) * N + c0 + nt * 8;
            *(float2*)p0 = make_float2(acc[mt][nt][0], acc[mt][nt][1]);
            *(float2*)p1 = make_float2(acc[mt][nt][2], acc[mt][nt][3]);
        }
}

// ============================================================================
// Phase A (MMA): per-(bh,c) S_c = kf^T @ v and z_c via ones-column.
// (unchanged from R5 — validated)
// ============================================================================
#define LDA_A 136
__global__ void __launch_bounds__(256, 1) chunk_state_mma()
{
    extern __shared__ char smraw[];
    __nv_bfloat16* sKh = (__nv_bfloat16*)smraw;       // 288*136
    __nv_bfloat16* sKl = sKh + 288 * LDA_A;
    __nv_bfloat16* sVh = sKl + 288 * LDA_A;           // 80*136
    __nv_bfloat16* sVl = sVh + 80 * LDA_A;

    const int bid = blockIdx.x;
    const int bh = bid >> 4, c = bid & 15;
    const int b = bh >> 4, h = bh & 15;
    const int tid = threadIdx.x, wid = tid >> 5, l = tid & 31;
    const int m0 = b * 2048 + c * 128;

    {
        const int j = tid >> 1, half = tid & 1;
        const float* kp = gQK + (size_t)(m0 + j) * 512 + 256 + h * 16;
        float kr[16];
#pragma unroll
        for (int f = 0; f < 16; f += 4) {
            float4 v4 = *(const float4*)(kp + f);
            kr[f] = v4.x; kr[f + 1] = v4.y; kr[f + 2] = v4.z; kr[f + 3] = v4.w;
        }
        for (int dd = 0; dd < 144; ++dd) {
            int d = half * 144 + dd;
            float val;
            if (d == 0) val = 1.f;
            else if (d < 17) val = kr[d - 1] * 0.5f;
            else if (d < 273) { int t = d - 17; val = kr[t >> 4] * kr[t & 15] * C2F; }
            else val = 0.f;
            __nv_bfloat16 hv = __float2bfloat16(val);
            sKh[d * LDA_A + j] = hv;
            sKl[d * LDA_A + j] = __float2bfloat16(val - __bfloat162float(hv));
        }
    }
    for (int idx = tid; idx < 8192; idx += 256) {
        int j = idx >> 6, e = idx & 63;
        float v = gV[(size_t)(m0 + j) * 1024 + h * 64 + e];
        __nv_bfloat16 hv = __float2bfloat16(v);
        sVh[e * LDA_A + j] = hv;
        sVl[e * LDA_A + j] = __float2bfloat16(v - __bfloat162float(hv));
    }
    for (int idx = tid; idx < 16 * 128; idx += 256) {
        int e = 64 + (idx >> 7), j = idx & 127;
        sVh[e * LDA_A + j] = __float2bfloat16(e == 64 ? 1.f : 0.f);
        sVl[e * LDA_A + j] = __float2bfloat16(0.f);
    }
    __syncthreads();

    const uint32_t aKh = smem_u32(sKh), aKl = smem_u32(sKl);
    const uint32_t aVh = smem_u32(sVh), aVl = smem_u32(sVl);
    const int nmf = (wid < 2) ? 3 : 2;

    float acc[3][9][4];
#pragma unroll
    for (int r = 0; r < 3; ++r)
#pragma unroll
        for (int nf = 0; nf < 9; ++nf)
#pragma unroll
            for (int cc = 0; cc < 4; ++cc) acc[r][nf][cc] = 0.f;

    for (int ks = 0; ks < 8; ++ks) {
        uint32_t ah[3][4], al[3][4];
#pragma unroll
        for (int r = 0; r < 3; ++r) if (r < nmf) {
            int mf = wid + 8 * r;
            uint32_t bo = (uint32_t)(mf * 16 + (l & 15)) * (LDA_A * 2)
                        + ks * 32 + ((l >> 4) << 4);
            ldsm4(ah[r], aKh + bo);
            ldsm4(al[r], aKl + bo);
        }
        uint32_t bhf[10][2], blf[10][2];
#pragma unroll
        for (int p = 0; p < 5; ++p) {
            uint32_t n = (uint32_t)(p * 16 + (l & 7) + ((l >> 4) << 3));
            uint32_t bo = n * (LDA_A * 2) + ks * 32 + (((l >> 3) & 1) << 4);
            uint32_t r4[4];
            ldsm4(r4, aVh + bo);
            bhf[2 * p][0] = r4[0]; bhf[2 * p][1] = r4[1];
            bhf[2 * p + 1][0] = r4[2]; bhf[2 * p + 1][1] = r4[3];
            ldsm4(r4, aVl + bo);
            blf[2 * p][0] = r4[0]; blf[2 * p][1] = r4[1];
            blf[2 * p + 1][0] = r4[2]; blf[2 * p + 1][1] = r4[3];
        }
#pragma unroll
        for (int r = 0; r < 3; ++r) if (r < nmf)
#pragma unroll
            for (int nf = 0; nf < 9; ++nf) {
                mma_bf16(acc[r][nf], ah[r], bhf[nf]);
                mma_bf16(acc[r][nf], ah[r], blf[nf]);
                mma_bf16(acc[r][nf], al[r], bhf[nf]);
            }
    }

    float* outS = gS + (size_t)bid * (DE * 64);
    float* outZ = gZ + (size_t)bid * DE;
#pragma unroll
    for (int r = 0; r < 3; ++r) if (r < nmf) {
        int mf = wid + 8 * r;
        int d0r = mf * 16 + (l >> 2);
#pragma unroll
        for (int nf = 0; nf < 9; ++nf) {
            int c0 = nf * 8 + 2 * (l & 3);
#pragma unroll
            for (int hh = 0; hh < 2; ++hh) {
                int d = d0r + hh * 8;
                if (d < DE) {
                    if (c0 < 64) {
                        outS[d * 64 + c0] = acc[r][nf][hh * 2];
                        outS[d * 64 + c0 + 1] = acc[r][nf][hh * 2 + 1];
                    } else if (c0 == 64) {
                        outZ[d] = acc[r][nf][hh * 2];
                    }
                }
            }
        }
    }
}

// ============================================================================
// Phase B: exclusive prefix over 16 chunks per (b,h); 4 CTAs per bh.
// ============================================================================
__global__ void __launch_bounds__(256) prefix_kernel()
{
    const int bh = blockIdx.x >> 2, part = blockIdx.x & 3;
    float* Sb = gS + (size_t)bh * 16 * (DE * 64);
    const int i0 = part * 4368, i1 = i0 + 4368;   // 17472/4
    for (int idx = i0 + threadIdx.x; idx < i1; idx += 256) {
        float run = 0.f;
#pragma unroll
        for (int c = 0; c < 16; ++c) {
            float* p = Sb + c * (DE * 64) + idx;
            float tmp = *p;
            *p = run;
            run += tmp;
        }
    }
    if (part == 0) {
        float* Zb = gZ + (size_t)bh * 16 * DE;
        for (int idx = threadIdx.x; idx < DE; idx += 256) {
            float run = 0.f;
#pragma unroll
            for (int c = 0; c < 16; ++c) {
                float* p = Zb + c * DE + idx;
                float tmp = *p;
                *p = run;
                run += tmp;
            }
        }
    }
}

// ============================================================================
// Phase C (MMA): per-(bh,c) output.
//  step1: q.k dots via MMA (48B-row bf16 hi/lo tiles, conflict-free),
//         poly+mask applied IN the accumulator fragment, repacked in-register
//         into the m16k16 A-operand layout for step2 (no smem round-trip).
//  step2: accY += attn @ [vT | ones]          (K=128, N=72)
//  step3: accY += qf @ [S^T | z], 2 d-tiles   (K=144 each)
//  y = accY / (accD + eps) -> gYh/gYl
// ============================================================================
#define LDA_C 152
#define LDQK 24
__global__ void __launch_bounds__(256, 1) chunk_out_mma()
{
    extern __shared__ char smraw[];
    __nv_bfloat16* sAh = (__nv_bfloat16*)smraw;        // 128*152
    __nv_bfloat16* sAl = sAh + 128 * LDA_C;
    __nv_bfloat16* sBh = sAl + 128 * LDA_C;            // 80*152
    __nv_bfloat16* sBl = sBh + 80 * LDA_C;
    float* sQ = (float*)(sBl + 80 * LDA_C);            // 128*17
    __nv_bfloat16* sQh = (__nv_bfloat16*)(sQ + 128 * 17); // 128*24 each
    __nv_bfloat16* sQl = sQh + 128 * LDQK;
    __nv_bfloat16* sKh = sQl + 128 * LDQK;
    __nv_bfloat16* sKl = sKh + 128 * LDQK;

    const int bid = blockIdx.x;
    const int bh = bid >> 4, c = bid & 15;
    const int b = bh >> 4, h = bh & 15;
    const int tid = threadIdx.x, wid = tid >> 5, l = tid & 31;
    const int m0 = b * 2048 + c * 128;

    // ---- load q,k; build bf16 hi/lo tiles + fp32 q ----
    for (int idx = tid; idx < 2048; idx += 256) {
        int i = idx >> 4, f = idx & 15;
        float qv = gQK[(size_t)(m0 + i) * 512 + h * 16 + f];
        float kv = gQK[(size_t)(m0 + i) * 512 + 256 + h * 16 + f];
        sQ[i * 17 + f] = qv;
        __nv_bfloat16 qh = __float2bfloat16(qv);
        sQh[i * LDQK + f] = qh;
        sQl[i * LDQK + f] = __float2bfloat16(qv - __bfloat162float(qh));
        __nv_bfloat16 kh = __float2bfloat16(kv);
        sKh[i * LDQK + f] = kh;
        sKl[i * LDQK + f] = __float2bfloat16(kv - __bfloat162float(kh));
    }
    // ---- vT + ones row 64 + zero rows 65..79 into sB ----
    for (int idx = tid; idx < 8192; idx += 256) {
        int j = idx >> 6, e = idx & 63;
        float v = gV[(size_t)(m0 + j) * 1024 + h * 64 + e];
        __nv_bfloat16 hv = __float2bfloat16(v);
        sBh[e * LDA_C + j] = hv;
        sBl[e * LDA_C + j] = __float2bfloat16(v - __bfloat162float(hv));
    }
    for (int idx = tid; idx < 16 * 144; idx += 256) {
        int e = 64 + (idx / 144), j = idx % 144;
        sBh[e * LDA_C + j] = __float2bfloat16(e == 64 ? 1.f : 0.f);
        sBl[e * LDA_C + j] = __float2bfloat16(0.f);
    }
    __syncthreads();

    const uint32_t aQh = smem_u32(sQh), aQl = smem_u32(sQl);
    const uint32_t aKh = smem_u32(sKh), aKl = smem_u32(sKl);
    const uint32_t aAh = smem_u32(sAh), aAl = smem_u32(sAl);
    const uint32_t aBh = smem_u32(sBh), aBl = smem_u32(sBl);

    // ---- step1: dot matrix via MMA ----
    float dacc[16][4];
#pragma unroll
    for (int nf = 0; nf < 16; ++nf)
#pragma unroll
        for (int cc = 0; cc < 4; ++cc) dacc[nf][cc] = 0.f;
    {
        uint32_t qh4[4], ql4[4];
        uint32_t bo = (uint32_t)(wid * 16 + (l & 15)) * (LDQK * 2) + ((l >> 4) << 4);
        ldsm4(qh4, aQh + bo);
        ldsm4(ql4, aQl + bo);
#pragma unroll
        for (int p = 0; p < 8; ++p) {
            uint32_t n = (uint32_t)(p * 16 + (l & 7) + ((l >> 4) << 3));
            uint32_t kb = n * (LDQK * 2) + (((l >> 3) & 1) << 4);
            uint32_t rk[4], rkl[4];
            ldsm4(rk, aKh + kb);
            ldsm4(rkl, aKl + kb);
            uint32_t b0[2] = {rk[0], rk[1]}, b1[2] = {rk[2], rk[3]};
            uint32_t c0[2] = {rkl[0], rkl[1]}, c1[2] = {rkl[2], rkl[3]};
            mma_bf16(dacc[2 * p], qh4, b0);
            mma_bf16(dacc[2 * p], qh4, c0);
            mma_bf16(dacc[2 * p], ql4, b0);
            mma_bf16(dacc[2 * p + 1], qh4, b1);
            mma_bf16(dacc[2 * p + 1], qh4, c1);
            mma_bf16(dacc[2 * p + 1], ql4, b1);
        }
    }
    // ---- poly + causal mask in the accumulator fragment ----
    const int r_lo = wid * 16 + (l >> 2);
#pragma unroll
    for (int nf = 0; nf < 16; ++nf) {
        int colb = nf * 8 + 2 * (l & 3);
#pragma unroll
        for (int cc = 0; cc < 4; ++cc) {
            int col = colb + (cc & 1);
            int row = r_lo + ((cc >> 1) << 3);
            float dot = dacc[nf][cc];
            float a = 1.f + dot * 0.25f + dot * dot * 0.03125f;
            dacc[nf][cc] = (col <= row) ? a : 0.f;
        }
    }
    // ---- repack into m16k16 A-operand fragments (in registers) ----
    uint32_t ah2[8][4], al2[8][4];
#pragma unroll
    for (int t = 0; t < 8; ++t) {
        ah2[t][0] = hipack(dacc[2 * t][0], dacc[2 * t][1]);
        ah2[t][1] = hipack(dacc[2 * t][2], dacc[2 * t][3]);
        ah2[t][2] = hipack(dacc[2 * t + 1][0], dacc[2 * t + 1][1]);
        ah2[t][3] = hipack(dacc[2 * t + 1][2], dacc[2 * t + 1][3]);
        al2[t][0] = lopack(dacc[2 * t][0], dacc[2 * t][1]);
        al2[t][1] = lopack(dacc[2 * t][2], dacc[2 * t][3]);
        al2[t][2] = lopack(dacc[2 * t + 1][0], dacc[2 * t + 1][1]);
        al2[t][3] = lopack(dacc[2 * t + 1][2], dacc[2 * t + 1][3]);
    }

    float acc[9][4];
#pragma unroll
    for (int nf = 0; nf < 9; ++nf)
#pragma unroll
        for (int cc = 0; cc < 4; ++cc) acc[nf][cc] = 0.f;

    // ---- step2: intra-chunk MMA (A frags already in registers) ----
#pragma unroll
    for (int ks = 0; ks < 8; ++ks) {
        uint32_t bhf[10][2], blf[10][2];
#pragma unroll
        for (int p = 0; p < 5; ++p) {
            uint32_t n = (uint32_t)(p * 16 + (l & 7) + ((l >> 4) << 3));
            uint32_t bo = n * (LDA_C * 2) + ks * 32 + (((l >> 3) & 1) << 4);
            uint32_t r4[4];
            ldsm4(r4, aBh + bo);
            bhf[2 * p][0] = r4[0]; bhf[2 * p][1] = r4[1];
            bhf[2 * p + 1][0] = r4[2]; bhf[2 * p + 1][1] = r4[3];
            ldsm4(r4, aBl + bo);
            blf[2 * p][0] = r4[0]; blf[2 * p][1] = r4[1];
            blf[2 * p + 1][0] = r4[2]; blf[2 * p + 1][1] = r4[3];
        }
#pragma unroll
        for (int nf = 0; nf < 9; ++nf) {
            mma_bf16(acc[nf], ah2[ks], bhf[nf]);
            mma_bf16(acc[nf], ah2[ks], blf[nf]);
            mma_bf16(acc[nf], al2[ks], bhf[nf]);
        }
    }
    __syncthreads();

    // ---- step3: inter-chunk, 2 d-tiles of 144 ----
    const float* Sp = gS + (size_t)bid * (DE * 64);
    const float* Zp = gZ + (size_t)bid * DE;
    for (int dt = 0; dt < 2; ++dt) {
        const int d0 = dt * 144;
        {
            const int i = tid >> 1, half = tid & 1;
            const float* qp = sQ + i * 17;
            for (int dd = 0; dd < 72; ++dd) {
                int dloc = half * 72 + dd;
                int d = d0 + dloc;
                float val;
                if (d == 0) val = 1.f;
                else if (d < 17) val = qp[d - 1] * 0.5f;
                else if (d < 273) { int t = d - 17; val = qp[t >> 4] * qp[t & 15] * C2F; }
                else val = 0.f;
                __nv_bfloat16 hv = __float2bfloat16(val);
                sAh[i * LDA_C + dloc] = hv;
                sAl[i * LDA_C + dloc] = __float2bfloat16(val - __bfloat162float(hv));
            }
        }
        for (int idx = tid; idx < 144 * 64; idx += 256) {
            int dd = idx >> 6, e = idx & 63;
            int d = d0 + dd;
            float v = (d < DE) ? Sp[d * 64 + e] : 0.f;
            __nv_bfloat16 hv = __float2bfloat16(v);
            sBh[e * LDA_C + dd] = hv;
            sBl[e * LDA_C + dd] = __float2bfloat16(v - __bfloat162float(hv));
        }
        for (int idx = tid; idx < 144; idx += 256) {
            int d = d0 + idx;
            float v = (d < DE) ? Zp[d] : 0.f;
            __nv_bfloat16 hv = __float2bfloat16(v);
            sBh[64 * LDA_C + idx] = hv;
            sBl[64 * LDA_C + idx] = __float2bfloat16(v - __bfloat162float(hv));
        }
        __syncthreads();

        for (int ks = 0; ks < 9; ++ks) {
            uint32_t ah[4], al[4];
            {
                uint32_t bo = (uint32_t)(wid * 16 + (l & 15)) * (LDA_C * 2)
                            + ks * 32 + ((l >> 4) << 4);
                ldsm4(ah, aAh + bo);
                ldsm4(al, aAl + bo);
            }
            uint32_t bhf[10][2], blf[10][2];
#pragma unroll
            for (int p = 0; p < 5; ++p) {
                uint32_t n = (uint32_t)(p * 16 + (l & 7) + ((l >> 4) << 3));
                uint32_t bo = n * (LDA_C * 2) + ks * 32 + (((l >> 3) & 1) << 4);
                uint32_t r4[4];
                ldsm4(r4, aBh + bo);
                bhf[2 * p][0] = r4[0]; bhf[2 * p][1] = r4[1];
                bhf[2 * p + 1][0] = r4[2]; bhf[2 * p + 1][1] = r4[3];
                ldsm4(r4, aBl + bo);
                blf[2 * p][0] = r4[0]; blf[2 * p][1] = r4[1];
                blf[2 * p + 1][0] = r4[2]; blf[2 * p + 1][1] = r4[3];
            }
#pragma unroll
            for (int nf = 0; nf < 9; ++nf) {
                mma_bf16(acc[nf], ah, bhf[nf]);
                mma_bf16(acc[nf], ah, blf[nf]);
                mma_bf16(acc[nf], al, bhf[nf]);
            }
        }
        __syncthreads();
    }

    // ---- divide + store y (bf16 hi/lo) ----
    float den0 = __shfl_sync(0xffffffffu, acc[8][0], l & 28);
    float den1 = __shfl_sync(0xffffffffu, acc[8][2], l & 28);
    float inv0 = 1.f / (den0 + EPSV);
    float inv1 = 1.f / (den1 + EPSV);
    const int r0 = wid * 16 + (l >> 2);
#pragma unroll
    for (int nf = 0; nf < 8; ++nf) {
        int c0 = nf * 8 + 2 * (l & 3);
#pragma unroll
        for (int hh = 0; hh < 2; ++hh) {
            int row = r0 + hh * 8;
            float inv = hh ? inv1 : inv0;
            size_t base = (size_t)(m0 + row) * 1024 + h * 64 + c0;
#pragma unroll
            for (int cc = 0; cc < 2; ++cc) {
                float yv = acc[nf][hh * 2 + cc] * inv;
                __nv_bfloat16 hv = __float2bfloat16(yv);
                gYh[base + cc] = hv;
                gYl[base + cc] = __float2bfloat16(yv - __bfloat162float(hv));
            }
        }
    }
}

// ============================================================================
// host launch
// ============================================================================
extern "C" void kernel_launch(void* const* d_in, const int* in_sizes, int n_in,
                              void* d_out, int out_size)
{
    const float* hs = (const float*)d_in[0];
    const float* Wq = (const float*)d_in[1];
    const float* Wk = (const float*)d_in[2];
    const float* Wv = (const float*)d_in[3];
    const float* Wo = (const float*)d_in[4];
    float* out = (float*)d_out;

    float *pQK, *pV;
    __nv_bfloat16 *pHh, *pHl, *pWh, *pWl, *pYh, *pYl;
    cudaGetSymbolAddress((void**)&pQK, gQK);
    cudaGetSymbolAddress((void**)&pV, gV);
    cudaGetSymbolAddress((void**)&pHh, gHh);
    cudaGetSymbolAddress((void**)&pHl, gHl);
    cudaGetSymbolAddress((void**)&pWh, gWh);
    cudaGetSymbolAddress((void**)&pWl, gWl);
    cudaGetSymbolAddress((void**)&pYh, gYh);
    cudaGetSymbolAddress((void**)&pYl, gYl);

    const int SMEM_G  = 98304;                                           // 3 x 32KB stages
    const int SMEM_CS = (2 * 288 * LDA_A + 2 * 80 * LDA_A) * 2;          // 200192
    const int SMEM_CO = (2 * 128 * LDA_C + 2 * 80 * LDA_C) * 2
                      + 128 * 17 * 4 + 4 * 128 * LDQK * 2;               // 159744
    cudaFuncSetAttribute(gemm_mma,
                         cudaFuncAttributeMaxDynamicSharedMemorySize, SMEM_G);
    cudaFuncSetAttribute(chunk_state_mma,
                         cudaFuncAttributeMaxDynamicSharedMemorySize, SMEM_CS);
    cudaFuncSetAttribute(chunk_out_mma,
                         cudaFuncAttributeMaxDynamicSharedMemorySize, SMEM_CO);

    dim3 blk(256);
    // hidden -> hi/lo bf16
    cvt_hilo<<<8192, blk>>>(hs, pHh, pHl);

    // fused Q|K projection (N = 512)
    cvt_hilo<<<256, blk>>>(Wq, pWh, pWl);
    cvt_hilo<<<256, blk>>>(Wk, pWh + 256 * 1024, pWl + 256 * 1024);
    gemm_mma<<<dim3(4, 64), blk, SMEM_G>>>(pHh, pHl, pWh, pWl, pQK, 512, 1024);

    // V projection
    cvt_hilo<<<1024, blk>>>(Wv, pWh, pWl);
    gemm_mma<<<dim3(8, 64), blk, SMEM_G>>>(pHh, pHl, pWh, pWl, pV, 1024, 1024);

    // chunked linear attention (MMA phases)
    chunk_state_mma<<<1024, blk, SMEM_CS>>>();
    prefix_kernel<<<256, blk>>>();
    chunk_out_mma<<<1024, blk, SMEM_CO>>>();

    // output projection
    cvt_hilo<<<1024, blk>>>(Wo, pWh, pWl);
    gemm_mma<<<dim3(8, 64), blk, SMEM_G>>>(pYh, pYl, pWh, pWl, out, 1024, 1024);
}

// round 10
// speedup vs baseline: 2.4864x; 1.0955x over previous
#include <cuda_runtime.h>
#include <cuda_bf16.h>
#include <cstdint>

#define DE 273
#define EPSV 1e-12f
#define C2F 0.17677669529663688f  // 1/(4*sqrt(2))

// ----- scratch (static device allocations; no cudaMalloc allowed) -----
__device__ float gQKV[8192 * 1536];    // [m][0:256 Q | 256:512 K | 512:1536 V]
__device__ float gS[1024 * DE * 64];   // [bh*16+c][273][64]
__device__ float gZ[1024 * DE];        // [bh*16+c][273]
__device__ __nv_bfloat16 gHh[8192 * 1024];
__device__ __nv_bfloat16 gHl[8192 * 1024];
__device__ __nv_bfloat16 gWh[1536 * 1024];
__device__ __nv_bfloat16 gWl[1536 * 1024];
__device__ __nv_bfloat16 gWoh[1024 * 1024];
__device__ __nv_bfloat16 gWol[1024 * 1024];
__device__ __nv_bfloat16 gYh[8192 * 1024];
__device__ __nv_bfloat16 gYl[8192 * 1024];

// ============================================================================
// helpers (portable PTX only: cp.async / ldmatrix / mma.sync)
// ============================================================================
__device__ __forceinline__ uint32_t smem_u32(const void* p) {
    uint32_t a;
    asm("{ .reg .u64 t; cvta.to.shared.u64 t, %1; cvt.u32.u64 %0, t; }" : "=r"(a) : "l"(p));
    return a;
}
__device__ __forceinline__ void cpasync16(uint32_t dst, const void* src) {
    asm volatile("cp.async.cg.shared.global [%0], [%1], 16;" :: "r"(dst), "l"(src));
}
__device__ __forceinline__ void cpasync_commit() {
    asm volatile("cp.async.commit_group;" ::: "memory");
}
__device__ __forceinline__ void cpasync_wait_all() {
    asm volatile("cp.async.wait_group 0;" ::: "memory");
}
__device__ __forceinline__ void ldsm4(uint32_t* r, uint32_t addr) {
    asm volatile("ldmatrix.sync.aligned.m8n8.x4.shared.b16 {%0,%1,%2,%3}, [%4];"
        : "=r"(r[0]), "=r"(r[1]), "=r"(r[2]), "=r"(r[3]) : "r"(addr));
}
__device__ __forceinline__ void mma_bf16(float* d, const uint32_t* a, const uint32_t* b) {
    asm volatile(
        "mma.sync.aligned.m16n8k16.row.col.f32.bf16.bf16.f32 "
        "{%0,%1,%2,%3}, {%4,%5,%6,%7}, {%8,%9}, {%0,%1,%2,%3};"
        : "+f"(d[0]), "+f"(d[1]), "+f"(d[2]), "+f"(d[3])
        : "r"(a[0]), "r"(a[1]), "r"(a[2]), "r"(a[3]), "r"(b[0]), "r"(b[1]));
}
__device__ __forceinline__ uint32_t sw128(uint32_t bo) { return bo ^ ((bo >> 3) & 0x70); }
__device__ __forceinline__ uint32_t hipack(float x, float y) {
    __nv_bfloat162 h(__float2bfloat16(x), __float2bfloat16(y));
    return *(uint32_t*)&h;
}
__device__ __forceinline__ uint32_t lopack(float x, float y) {
    float xr = x - __bfloat162float(__float2bfloat16(x));
    float yr = y - __bfloat162float(__float2bfloat16(y));
    __nv_bfloat162 h(__float2bfloat16(xr), __float2bfloat16(yr));
    return *(uint32_t*)&h;
}

// ============================================================================
// fp32 -> (hi, lo) bf16 split conversion.  one block = 1024 elements.
// ============================================================================
__global__ void __launch_bounds__(256) cvt_hilo(
    const float* __restrict__ src, __nv_bfloat16* __restrict__ hi,
    __nv_bfloat16* __restrict__ lo)
{
    int i = (blockIdx.x * 256 + threadIdx.x) * 4;
    float4 v = *(const float4*)(src + i);
    __nv_bfloat16 h0 = __float2bfloat16(v.x), h1 = __float2bfloat16(v.y);
    __nv_bfloat16 h2 = __float2bfloat16(v.z), h3 = __float2bfloat16(v.w);
    __nv_bfloat16 l0 = __float2bfloat16(v.x - __bfloat162float(h0));
    __nv_bfloat16 l1 = __float2bfloat16(v.y - __bfloat162float(h1));
    __nv_bfloat16 l2 = __float2bfloat16(v.z - __bfloat162float(h2));
    __nv_bfloat16 l3 = __float2bfloat16(v.w - __bfloat162float(h3));
    __nv_bfloat162* ph = (__nv_bfloat162*)(hi + i);
    __nv_bfloat162* pl = (__nv_bfloat162*)(lo + i);
    ph[0] = __nv_bfloat162(h0, h1); ph[1] = __nv_bfloat162(h2, h3);
    pl[0] = __nv_bfloat162(l0, l1); pl[1] = __nv_bfloat162(l2, l3);
}

// ============================================================================
// split-bf16 HMMA GEMM (NT): C = Ah*Bh + Ah*Bl + Al*Bh, fp32-quality.
// CTA tile 128x128, K in stages of 64, 2-stage cp.async, SW128 rows.
// 512 threads, 16 warps (4m x 4n), warp tile 32x32.
// ============================================================================
__global__ void __launch_bounds__(512, 1) gemm_mma(
    const __nv_bfloat16* __restrict__ Ah, const __nv_bfloat16* __restrict__ Al,
    const __nv_bfloat16* __restrict__ Bh, const __nv_bfloat16* __restrict__ Bl,
    float* __restrict__ C, int N, int K)
{
    extern __shared__ char smem[];
    const uint32_t sb = smem_u32(smem);
    const int tid = threadIdx.x, wid = tid >> 5, l = tid & 31;
    const int wm = wid & 3, wn = wid >> 2;
    const int bm = blockIdx.y * 128, bn = blockIdx.x * 128;

    const __nv_bfloat16* gp0[4] = {
        Ah + (size_t)bm * K, Al + (size_t)bm * K,
        Bh + (size_t)bn * K, Bl + (size_t)bn * K };

    const int NST = K >> 6;

    float acc[2][4][4];
#pragma unroll
    for (int mt = 0; mt < 2; ++mt)
#pragma unroll
        for (int nt = 0; nt < 4; ++nt)
#pragma unroll
            for (int c = 0; c < 4; ++c) acc[mt][nt][c] = 0.f;

    {
        const uint32_t sdst = sb;
#pragma unroll
        for (int t = 0; t < 4; ++t)
#pragma unroll
            for (int it = 0; it < 2; ++it) {
                int ch = tid + it * 512;
                int row = ch >> 3, cb = ch & 7;
                cpasync16(sdst + t * 16384 + sw128(row * 128 + cb * 16),
                          gp0[t] + (size_t)row * K + cb * 8);
            }
        cpasync_commit();
    }

    for (int s = 0; s < NST; ++s) {
        cpasync_wait_all();
        __syncthreads();
        if (s + 1 < NST) {
            const uint32_t sdst = sb + (uint32_t)((s + 1) & 1) * 65536u;
            const int k0 = (s + 1) * 64;
#pragma unroll
            for (int t = 0; t < 4; ++t)
#pragma unroll
                for (int it = 0; it < 2; ++it) {
                    int ch = tid + it * 512;
                    int row = ch >> 3, cb = ch & 7;
                    cpasync16(sdst + t * 16384 + sw128(row * 128 + cb * 16),
                              gp0[t] + (size_t)row * K + k0 + cb * 8);
                }
            cpasync_commit();
        }
        const uint32_t sc = sb + (uint32_t)(s & 1) * 65536u;
#pragma unroll
        for (int ks = 0; ks < 4; ++ks) {
            uint32_t ah[2][4], al[2][4];
#pragma unroll
            for (int mt = 0; mt < 2; ++mt) {
                uint32_t bo = (uint32_t)(wm * 32 + mt * 16 + (l & 15)) * 128
                            + ks * 32 + ((l >> 4) << 4);
                bo = sw128(bo);
                ldsm4(ah[mt], sc + bo);
                ldsm4(al[mt], sc + 16384 + bo);
            }
#pragma unroll
            for (int p = 0; p < 2; ++p) {
                uint32_t n = (uint32_t)(wn * 32 + p * 16 + (l & 7) + ((l >> 4) << 3));
                uint32_t bo = n * 128 + ks * 32 + (((l >> 3) & 1) << 4);
                bo = sw128(bo);
                uint32_t rb[4], rl[4];
                ldsm4(rb, sc + 32768 + bo);
                ldsm4(rl, sc + 49152 + bo);
                uint32_t b0[2] = {rb[0], rb[1]}, b1[2] = {rb[2], rb[3]};
                uint32_t c0[2] = {rl[0], rl[1]}, c1[2] = {rl[2], rl[3]};
#pragma unroll
                for (int mt = 0; mt < 2; ++mt) {
                    mma_bf16(acc[mt][2 * p],     ah[mt], b0);
                    mma_bf16(acc[mt][2 * p + 1], ah[mt], b1);
                    mma_bf16(acc[mt][2 * p],     ah[mt], c0);
                    mma_bf16(acc[mt][2 * p + 1], ah[mt], c1);
                    mma_bf16(acc[mt][2 * p],     al[mt], b0);
                    mma_bf16(acc[mt][2 * p + 1], al[mt], b1);
                }
            }
        }
        __syncthreads();
    }

    const int r0 = bm + wm * 32 + (l >> 2);
    const int c0 = bn + wn * 32 + 2 * (l & 3);
#pragma unroll
    for (int mt = 0; mt < 2; ++mt)
#pragma unroll
        for (int nt = 0; nt < 4; ++nt) {
            float* p0 = C + (size_t)(r0 + mt * 16) * N + c0 + nt * 8;
            float* p1 = C + (size_t)(r0 + mt * 16 + 8) * N + c0 + nt * 8;
            *(float2*)p0 = make_float2(acc[mt][nt][0], acc[mt][nt][1]);
            *(float2*)p1 = make_float2(acc[mt][nt][2], acc[mt][nt][3]);
        }
}

// ============================================================================
// Phase A (MMA): per-(bh,c) S_c = kf^T @ v, z_c via ones-column.
// 512 threads, 16 warps = 8 m-slots x 2 n-halves (B frags 6 each, overlap 2).
// ============================================================================
#define LDA_A 136
__global__ void __launch_bounds__(512, 1) chunk_state_mma()
{
    extern __shared__ char smraw[];
    __nv_bfloat16* sKh = (__nv_bfloat16*)smraw;       // 288*136
    __nv_bfloat16* sKl = sKh + 288 * LDA_A;
    __nv_bfloat16* sVh = sKl + 288 * LDA_A;           // 80*136
    __nv_bfloat16* sVl = sVh + 80 * LDA_A;

    const int bid = blockIdx.x;
    const int bh = bid >> 4, c = bid & 15;
    const int b = bh >> 4, h = bh & 15;
    const int tid = threadIdx.x, wid = tid >> 5, l = tid & 31;
    const int wgrp = wid & 7, nh = wid >> 3;
    const int m0 = b * 2048 + c * 128;

    // ---- build kf^T hi/lo (each thread: 72 features of one position) ----
    {
        const int j = tid >> 2, qtr = tid & 3;
        const float* kp = gQKV + (size_t)(m0 + j) * 1536 + 256 + h * 16;
        float kr[16];
#pragma unroll
        for (int f = 0; f < 16; f += 4) {
            float4 v4 = *(const float4*)(kp + f);
            kr[f] = v4.x; kr[f + 1] = v4.y; kr[f + 2] = v4.z; kr[f + 3] = v4.w;
        }
        for (int dd = 0; dd < 72; ++dd) {
            int d = qtr * 72 + dd;
            float val;
            if (d == 0) val = 1.f;
            else if (d < 17) val = kr[d - 1] * 0.5f;
            else if (d < 273) { int t = d - 17; val = kr[t >> 4] * kr[t & 15] * C2F; }
            else val = 0.f;
            __nv_bfloat16 hv = __float2bfloat16(val);
            sKh[d * LDA_A + j] = hv;
            sKl[d * LDA_A + j] = __float2bfloat16(val - __bfloat162float(hv));
        }
    }
    for (int idx = tid; idx < 8192; idx += 512) {
        int j = idx >> 6, e = idx & 63;
        float v = gQKV[(size_t)(m0 + j) * 1536 + 512 + h * 64 + e];
        __nv_bfloat16 hv = __float2bfloat16(v);
        sVh[e * LDA_A + j] = hv;
        sVl[e * LDA_A + j] = __float2bfloat16(v - __bfloat162float(hv));
    }
    for (int idx = tid; idx < 16 * 128; idx += 512) {
        int e = 64 + (idx >> 7), j = idx & 127;
        sVh[e * LDA_A + j] = __float2bfloat16(e == 64 ? 1.f : 0.f);
        sVl[e * LDA_A + j] = __float2bfloat16(0.f);
    }
    __syncthreads();

    const uint32_t aKh = smem_u32(sKh), aKl = smem_u32(sKl);
    const uint32_t aVh = smem_u32(sVh), aVl = smem_u32(sVl);
    const int nmf = (wgrp < 2) ? 3 : 2;
    const int pstart = nh * 2;       // B n-frag p range: nh0 p0-2, nh1 p2-4

    float acc[3][6][4];
#pragma unroll
    for (int r = 0; r < 3; ++r)
#pragma unroll
        for (int nf = 0; nf < 6; ++nf)
#pragma unroll
            for (int cc = 0; cc < 4; ++cc) acc[r][nf][cc] = 0.f;

    for (int ks = 0; ks < 8; ++ks) {
        uint32_t ah[3][4], al[3][4];
#pragma unroll
        for (int r = 0; r < 3; ++r) if (r < nmf) {
            int mf = wgrp + 8 * r;
            uint32_t bo = (uint32_t)(mf * 16 + (l & 15)) * (LDA_A * 2)
                        + ks * 32 + ((l >> 4) << 4);
            ldsm4(ah[r], aKh + bo);
            ldsm4(al[r], aKl + bo);
        }
        uint32_t bhf[6][2], blf[6][2];
#pragma unroll
        for (int pp = 0; pp < 3; ++pp) {
            int p = pstart + pp;
            uint32_t n = (uint32_t)(p * 16 + (l & 7) + ((l >> 4) << 3));
            uint32_t bo = n * (LDA_A * 2) + ks * 32 + (((l >> 3) & 1) << 4);
            uint32_t r4[4];
            ldsm4(r4, aVh + bo);
            bhf[2 * pp][0] = r4[0]; bhf[2 * pp][1] = r4[1];
            bhf[2 * pp + 1][0] = r4[2]; bhf[2 * pp + 1][1] = r4[3];
            ldsm4(r4, aVl + bo);
            blf[2 * pp][0] = r4[0]; blf[2 * pp][1] = r4[1];
            blf[2 * pp + 1][0] = r4[2]; blf[2 * pp + 1][1] = r4[3];
        }
#pragma unroll
        for (int r = 0; r < 3; ++r) if (r < nmf)
#pragma unroll
            for (int nf = 0; nf < 6; ++nf) {
                mma_bf16(acc[r][nf], ah[r], bhf[nf]);
                mma_bf16(acc[r][nf], ah[r], blf[nf]);
                mma_bf16(acc[r][nf], al[r], bhf[nf]);
            }
    }

    // ---- writeback: nh0 owns g=0..4, nh1 owns g=5..8 (g = global n-frag) ----
    float* outS = gS + (size_t)bid * (DE * 64);
    float* outZ = gZ + (size_t)bid * DE;
#pragma unroll
    for (int r = 0; r < 3; ++r) if (r < nmf) {
        int mf = wgrp + 8 * r;
        int d0r = mf * 16 + (l >> 2);
#pragma unroll
        for (int nf = 0; nf < 6; ++nf) {
            int g = 2 * pstart + nf;
            bool own = nh == 0 ? (g <= 4) : (g >= 5 && g <= 8);
            if (!own) continue;
            int c0 = g * 8 + 2 * (l & 3);
#pragma unroll
            for (int hh = 0; hh < 2; ++hh) {
                int d = d0r + hh * 8;
                if (d < DE) {
                    if (c0 < 64) {
                        outS[d * 64 + c0] = acc[r][nf][hh * 2];
                        outS[d * 64 + c0 + 1] = acc[r][nf][hh * 2 + 1];
                    } else if (c0 == 64) {
                        outZ[d] = acc[r][nf][hh * 2];
                    }
                }
            }
        }
    }
}

// ============================================================================
// Phase B: exclusive prefix over 16 chunks per (b,h); 8 CTAs per bh.
// ============================================================================
__global__ void __launch_bounds__(256) prefix_kernel()
{
    const int bh = blockIdx.x >> 3, part = blockIdx.x & 7;
    float* Sb = gS + (size_t)bh * 16 * (DE * 64);
    const int i0 = part * 2184, i1 = i0 + 2184;   // 17472/8
    for (int idx = i0 + threadIdx.x; idx < i1; idx += 256) {
        float run = 0.f;
#pragma unroll
        for (int c = 0; c < 16; ++c) {
            float* p = Sb + c * (DE * 64) + idx;
            float tmp = *p;
            *p = run;
            run += tmp;
        }
    }
    if (part == 0) {
        float* Zb = gZ + (size_t)bh * 16 * DE;
        for (int idx = threadIdx.x; idx < DE; idx += 256) {
            float run = 0.f;
#pragma unroll
            for (int c = 0; c < 16; ++c) {
                float* p = Zb + c * DE + idx;
                float tmp = *p;
                *p = run;
                run += tmp;
            }
        }
    }
}

// ============================================================================
// Phase C (MMA): per-(bh,c) output.  512 threads, 16 warps = 8 m-slots x 2
// n-halves.  step1 (q.k dot MMA + poly/mask in-fragment + register repack)
// duplicated across the pair; step2/step3 B-side split 5/4; den via smem.
// ============================================================================
#define LDA_C 152
#define LDQK 24
__global__ void __launch_bounds__(512, 1) chunk_out_mma()
{
    extern __shared__ char smraw[];
    __nv_bfloat16* sAh = (__nv_bfloat16*)smraw;        // 128*152
    __nv_bfloat16* sAl = sAh + 128 * LDA_C;
    __nv_bfloat16* sBh = sAl + 128 * LDA_C;            // 80*152
    __nv_bfloat16* sBl = sBh + 80 * LDA_C;
    float* sQ = (float*)(sBl + 80 * LDA_C);            // 128*17 (reused for den)
    __nv_bfloat16* sQh = (__nv_bfloat16*)(sQ + 128 * 17); // 128*24 each
    __nv_bfloat16* sQl = sQh + 128 * LDQK;
    __nv_bfloat16* sKh = sQl + 128 * LDQK;
    __nv_bfloat16* sKl = sKh + 128 * LDQK;

    const int bid = blockIdx.x;
    const int bh = bid >> 4, c = bid & 15;
    const int b = bh >> 4, h = bh & 15;
    const int tid = threadIdx.x, wid = tid >> 5, l = tid & 31;
    const int wgrp = wid & 7, nh = wid >> 3;
    const int m0 = b * 2048 + c * 128;

    // ---- load q,k; build bf16 hi/lo tiles + fp32 q ----
    for (int idx = tid; idx < 2048; idx += 512) {
        int i = idx >> 4, f = idx & 15;
        float qv = gQKV[(size_t)(m0 + i) * 1536 + h * 16 + f];
        float kv = gQKV[(size_t)(m0 + i) * 1536 + 256 + h * 16 + f];
        sQ[i * 17 + f] = qv;
        __nv_bfloat16 qh = __float2bfloat16(qv);
        sQh[i * LDQK + f] = qh;
        sQl[i * LDQK + f] = __float2bfloat16(qv - __bfloat162float(qh));
        __nv_bfloat16 kh = __float2bfloat16(kv);
        sKh[i * LDQK + f] = kh;
        sKl[i * LDQK + f] = __float2bfloat16(kv - __bfloat162float(kh));
    }
    for (int idx = tid; idx < 8192; idx += 512) {
        int j = idx >> 6, e = idx & 63;
        float v = gQKV[(size_t)(m0 + j) * 1536 + 512 + h * 64 + e];
        __nv_bfloat16 hv = __float2bfloat16(v);
        sBh[e * LDA_C + j] = hv;
        sBl[e * LDA_C + j] = __float2bfloat16(v - __bfloat162float(hv));
    }
    for (int idx = tid; idx < 16 * 144; idx += 512) {
        int e = 64 + (idx / 144), j = idx % 144;
        sBh[e * LDA_C + j] = __float2bfloat16(e == 64 ? 1.f : 0.f);
        sBl[e * LDA_C + j] = __float2bfloat16(0.f);
    }
    __syncthreads();

    const uint32_t aQh = smem_u32(sQh), aQl = smem_u32(sQl);
    const uint32_t aKh = smem_u32(sKh), aKl = smem_u32(sKl);
    const uint32_t aAh = smem_u32(sAh), aAl = smem_u32(sAl);
    const uint32_t aBh = smem_u32(sBh), aBl = smem_u32(sBl);
    const int pstart = nh * 2;

    // ---- step1: dot MMA + poly/mask + repack, in two 4-ks halves ----
    uint32_t ah2[8][4], al2[8][4];
    {
        uint32_t qh4[4], ql4[4];
        uint32_t bo = (uint32_t)(wgrp * 16 + (l & 15)) * (LDQK * 2) + ((l >> 4) << 4);
        ldsm4(qh4, aQh + bo);
        ldsm4(ql4, aQl + bo);
        const int r_lo = wgrp * 16 + (l >> 2);
#pragma unroll
        for (int h2 = 0; h2 < 2; ++h2) {
            float dacc[8][4];
#pragma unroll
            for (int nf = 0; nf < 8; ++nf)
#pragma unroll
                for (int cc = 0; cc < 4; ++cc) dacc[nf][cc] = 0.f;
#pragma unroll
            for (int pp = 0; pp < 4; ++pp) {
                int p = h2 * 4 + pp;
                uint32_t n = (uint32_t)(p * 16 + (l & 7) + ((l >> 4) << 3));
                uint32_t kb = n * (LDQK * 2) + (((l >> 3) & 1) << 4);
                uint32_t rk[4], rkl[4];
                ldsm4(rk, aKh + kb);
                ldsm4(rkl, aKl + kb);
                uint32_t b0[2] = {rk[0], rk[1]}, b1[2] = {rk[2], rk[3]};
                uint32_t c0[2] = {rkl[0], rkl[1]}, c1[2] = {rkl[2], rkl[3]};
                mma_bf16(dacc[2 * pp], qh4, b0);
                mma_bf16(dacc[2 * pp], qh4, c0);
                mma_bf16(dacc[2 * pp], ql4, b0);
                mma_bf16(dacc[2 * pp + 1], qh4, b1);
                mma_bf16(dacc[2 * pp + 1], qh4, c1);
                mma_bf16(dacc[2 * pp + 1], ql4, b1);
            }
#pragma unroll
            for (int nf = 0; nf < 8; ++nf) {
                int colb = (h2 * 8 + nf) * 8 + 2 * (l & 3);
#pragma unroll
                for (int cc = 0; cc < 4; ++cc) {
                    int col = colb + (cc & 1);
                    int row = r_lo + ((cc >> 1) << 3);
                    float dot = dacc[nf][cc];
                    float a = 1.f + dot * 0.25f + dot * dot * 0.03125f;
                    dacc[nf][cc] = (col <= row) ? a : 0.f;
                }
            }
#pragma unroll
            for (int t = 0; t < 4; ++t) {
                int ksg = h2 * 4 + t;
                ah2[ksg][0] = hipack(dacc[2 * t][0], dacc[2 * t][1]);
                ah2[ksg][1] = hipack(dacc[2 * t][2], dacc[2 * t][3]);
                ah2[ksg][2] = hipack(dacc[2 * t + 1][0], dacc[2 * t + 1][1]);
                ah2[ksg][3] = hipack(dacc[2 * t + 1][2], dacc[2 * t + 1][3]);
                al2[ksg][0] = lopack(dacc[2 * t][0], dacc[2 * t][1]);
                al2[ksg][1] = lopack(dacc[2 * t][2], dacc[2 * t][3]);
                al2[ksg][2] = lopack(dacc[2 * t + 1][0], dacc[2 * t + 1][1]);
                al2[ksg][3] = lopack(dacc[2 * t + 1][2], dacc[2 * t + 1][3]);
            }
        }
    }

    float acc[6][4];
#pragma unroll
    for (int nf = 0; nf < 6; ++nf)
#pragma unroll
        for (int cc = 0; cc < 4; ++cc) acc[nf][cc] = 0.f;

    // ---- step2: intra-chunk MMA (A in registers, B n-half) ----
#pragma unroll
    for (int ks = 0; ks < 8; ++ks) {
        uint32_t bhf[6][2], blf[6][2];
#pragma unroll
        for (int pp = 0; pp < 3; ++pp) {
            int p = pstart + pp;
            uint32_t n = (uint32_t)(p * 16 + (l & 7) + ((l >> 4) << 3));
            uint32_t bo = n * (LDA_C * 2) + ks * 32 + (((l >> 3) & 1) << 4);
            uint32_t r4[4];
            ldsm4(r4, aBh + bo);
            bhf[2 * pp][0] = r4[0]; bhf[2 * pp][1] = r4[1];
            bhf[2 * pp + 1][0] = r4[2]; bhf[2 * pp + 1][1] = r4[3];
            ldsm4(r4, aBl + bo);
            blf[2 * pp][0] = r4[0]; blf[2 * pp][1] = r4[1];
            blf[2 * pp + 1][0] = r4[2]; blf[2 * pp + 1][1] = r4[3];
        }
#pragma unroll
        for (int nf = 0; nf < 6; ++nf) {
            mma_bf16(acc[nf], ah2[ks], bhf[nf]);
            mma_bf16(acc[nf], ah2[ks], blf[nf]);
            mma_bf16(acc[nf], al2[ks], bhf[nf]);
        }
    }
    __syncthreads();

    // ---- step3: inter-chunk, 2 d-tiles of 144 ----
    const float* Sp = gS + (size_t)bid * (DE * 64);
    const float* Zp = gZ + (size_t)bid * DE;
    for (int dt = 0; dt < 2; ++dt) {
        const int d0 = dt * 144;
        {
            const int i = tid >> 2, qtr = tid & 3;
            const float* qp = sQ + i * 17;
            for (int dd = 0; dd < 36; ++dd) {
                int dloc = qtr * 36 + dd;
                int d = d0 + dloc;
                float val;
                if (d == 0) val = 1.f;
                else if (d < 17) val = qp[d - 1] * 0.5f;
                else if (d < 273) { int t = d - 17; val = qp[t >> 4] * qp[t & 15] * C2F; }
                else val = 0.f;
                __nv_bfloat16 hv = __float2bfloat16(val);
                sAh[i * LDA_C + dloc] = hv;
                sAl[i * LDA_C + dloc] = __float2bfloat16(val - __bfloat162float(hv));
            }
        }
        for (int idx = tid; idx < 144 * 64; idx += 512) {
            int dd = idx >> 6, e = idx & 63;
            int d = d0 + dd;
            float v = (d < DE) ? Sp[d * 64 + e] : 0.f;
            __nv_bfloat16 hv = __float2bfloat16(v);
            sBh[e * LDA_C + dd] = hv;
            sBl[e * LDA_C + dd] = __float2bfloat16(v - __bfloat162float(hv));
        }
        for (int idx = tid; idx < 144; idx += 512) {
            int d = d0 + idx;
            float v = (d < DE) ? Zp[d] : 0.f;
            __nv_bfloat16 hv = __float2bfloat16(v);
            sBh[64 * LDA_C + idx] = hv;
            sBl[64 * LDA_C + idx] = __float2bfloat16(v - __bfloat162float(hv));
        }
        __syncthreads();

        for (int ks = 0; ks < 9; ++ks) {
            uint32_t ah[4], al[4];
            {
                uint32_t bo = (uint32_t)(wgrp * 16 + (l & 15)) * (LDA_C * 2)
                            + ks * 32 + ((l >> 4) << 4);
                ldsm4(ah, aAh + bo);
                ldsm4(al, aAl + bo);
            }
            uint32_t bhf[6][2], blf[6][2];
#pragma unroll
            for (int pp = 0; pp < 3; ++pp) {
                int p = pstart + pp;
                uint32_t n = (uint32_t)(p * 16 + (l & 7) + ((l >> 4) << 3));
                uint32_t bo = n * (LDA_C * 2) + ks * 32 + (((l >> 3) & 1) << 4);
                uint32_t r4[4];
                ldsm4(r4, aBh + bo);
                bhf[2 * pp][0] = r4[0]; bhf[2 * pp][1] = r4[1];
                bhf[2 * pp + 1][0] = r4[2]; bhf[2 * pp + 1][1] = r4[3];
                ldsm4(r4, aBl + bo);
                blf[2 * pp][0] = r4[0]; blf[2 * pp][1] = r4[1];
                blf[2 * pp + 1][0] = r4[2]; blf[2 * pp + 1][1] = r4[3];
            }
#pragma unroll
            for (int nf = 0; nf < 6; ++nf) {
                mma_bf16(acc[nf], ah, bhf[nf]);
                mma_bf16(acc[nf], ah, blf[nf]);
                mma_bf16(acc[nf], al, bhf[nf]);
            }
        }
        __syncthreads();
    }

    // ---- denominator exchange (nh1 owns g=8) then divide + store ----
    const int rowbase = wgrp * 16;
    if (nh == 1) {
        // g=8 -> local nf = 8 - 2*pstart = 4
        float den0 = __shfl_sync(0xffffffffu, acc[4][0], l & 28);
        float den1 = __shfl_sync(0xffffffffu, acc[4][2], l & 28);
        if ((l & 3) == 0) {
            sQ[rowbase + (l >> 2)] = 1.f / (den0 + EPSV);
            sQ[rowbase + (l >> 2) + 8] = 1.f / (den1 + EPSV);
        }
    }
    __syncthreads();
    float inv0 = sQ[rowbase + (l >> 2)];
    float inv1 = sQ[rowbase + (l >> 2) + 8];
    const int r0 = rowbase + (l >> 2);
#pragma unroll
    for (int nf = 0; nf < 6; ++nf) {
        int g = 2 * pstart + nf;
        bool own = nh == 0 ? (g <= 4) : (g >= 5 && g <= 7);
        if (!own) continue;
        int c0 = g * 8 + 2 * (l & 3);
#pragma unroll
        for (int hh = 0; hh < 2; ++hh) {
            int row = r0 + hh * 8;
            float inv = hh ? inv1 : inv0;
            size_t base = (size_t)(m0 + row) * 1024 + h * 64 + c0;
#pragma unroll
            for (int cc = 0; cc < 2; ++cc) {
                float yv = acc[nf][hh * 2 + cc] * inv;
                __nv_bfloat16 hv = __float2bfloat16(yv);
                gYh[base + cc] = hv;
                gYl[base + cc] = __float2bfloat16(yv - __bfloat162float(hv));
            }
        }
    }
}

// ============================================================================
// host launch
// ============================================================================
extern "C" void kernel_launch(void* const* d_in, const int* in_sizes, int n_in,
                              void* d_out, int out_size)
{
    const float* hs = (const float*)d_in[0];
    const float* Wq = (const float*)d_in[1];
    const float* Wk = (const float*)d_in[2];
    const float* Wv = (const float*)d_in[3];
    const float* Wo = (const float*)d_in[4];
    float* out = (float*)d_out;

    float* pQKV;
    __nv_bfloat16 *pHh, *pHl, *pWh, *pWl, *pWoh, *pWol, *pYh, *pYl;
    cudaGetSymbolAddress((void**)&pQKV, gQKV);
    cudaGetSymbolAddress((void**)&pHh, gHh);
    cudaGetSymbolAddress((void**)&pHl, gHl);
    cudaGetSymbolAddress((void**)&pWh, gWh);
    cudaGetSymbolAddress((void**)&pWl, gWl);
    cudaGetSymbolAddress((void**)&pWoh, gWoh);
    cudaGetSymbolAddress((void**)&pWol, gWol);
    cudaGetSymbolAddress((void**)&pYh, gYh);
    cudaGetSymbolAddress((void**)&pYl, gYl);

    const int SMEM_G  = 131072;                                          // 2 x 64KB
    const int SMEM_CS = (2 * 288 * LDA_A + 2 * 80 * LDA_A) * 2;          // 200192
    const int SMEM_CO = (2 * 128 * LDA_C + 2 * 80 * LDA_C) * 2
                      + 128 * 17 * 4 + 4 * 128 * LDQK * 2;               // 159744
    cudaFuncSetAttribute(gemm_mma,
                         cudaFuncAttributeMaxDynamicSharedMemorySize, SMEM_G);
    cudaFuncSetAttribute(chunk_state_mma,
                         cudaFuncAttributeMaxDynamicSharedMemorySize, SMEM_CS);
    cudaFuncSetAttribute(chunk_out_mma,
                         cudaFuncAttributeMaxDynamicSharedMemorySize, SMEM_CO);

    // conversions
    cvt_hilo<<<8192, 256>>>(hs, pHh, pHl);
    cvt_hilo<<<256, 256>>>(Wq, pWh, pWl);
    cvt_hilo<<<256, 256>>>(Wk, pWh + 256 * 1024, pWl + 256 * 1024);
    cvt_hilo<<<1024, 256>>>(Wv, pWh + 512 * 1024, pWl + 512 * 1024);
    cvt_hilo<<<1024, 256>>>(Wo, pWoh, pWol);

    // fused Q|K|V projection (N = 1536)
    gemm_mma<<<dim3(12, 64), 512, SMEM_G>>>(pHh, pHl, pWh, pWl, pQKV, 1536, 1024);

    // chunked linear attention
    chunk_state_mma<<<1024, 512, SMEM_CS>>>();
    prefix_kernel<<<512, 256>>>();
    chunk_out_mma<<<1024, 512, SMEM_CO>>>();

    // output projection
    gemm_mma<<<dim3(8, 64), 512, SMEM_G>>>(pYh, pYl, pWoh, pWol, out, 1024, 1024);
}